// round 11
// baseline (speedup 1.0000x reference)
#include <cuda_runtime.h>
#include <cuda_bf16.h>
#include <math.h>
#include <stdint.h>

#define S_LEN 2048
#define HID   3584
#define NH    28
#define NKV   4
#define HD    128
#define KV_DIM 512
#define QKV_N  4608   // 3584 + 512 + 512

// ---------------- scratch (__device__ globals; no allocs allowed) ----------
__device__ __nv_bfloat16 g_Xhi[S_LEN * HID];
__device__ __nv_bfloat16 g_Xlo[S_LEN * HID];
__device__ __nv_bfloat16 g_Ahi[S_LEN * HID];
__device__ __nv_bfloat16 g_Alo[S_LEN * HID];
__device__ __nv_bfloat16 g_Wt_hi[(size_t)QKV_N * HID];
__device__ __nv_bfloat16 g_Wt_lo[(size_t)QKV_N * HID];
__device__ __nv_bfloat16 g_Wo_hi[(size_t)HID * HID];
__device__ __nv_bfloat16 g_Wo_lo[(size_t)HID * HID];

__device__ __nv_bfloat16 g_Qh[S_LEN * HID];
__device__ __nv_bfloat16 g_Ql[S_LEN * HID];
__device__ __nv_bfloat16 g_Kh[S_LEN * KV_DIM];
__device__ __nv_bfloat16 g_Kl[S_LEN * KV_DIM];
__device__ __nv_bfloat16 g_Vh[S_LEN * KV_DIM];
__device__ __nv_bfloat16 g_Vl[S_LEN * KV_DIM];

__device__ float g_rope_cos[S_LEN * 64];
__device__ float g_rope_sin[S_LEN * 64];

// ---------------- PTX helpers (baseline PTX only) ---------------------------
__device__ __forceinline__ uint32_t smem_u32(const void* p) {
    uint32_t a;
    asm("{ .reg .u64 t; cvta.to.shared.u64 t, %1; cvt.u32.u64 %0, t; }" : "=r"(a) : "l"(p));
    return a;
}
__device__ __forceinline__ void cp_async16(uint32_t dst, const void* src) {
    asm volatile("cp.async.cg.shared.global [%0], [%1], 16;" :: "r"(dst), "l"(src));
}
#define CP_COMMIT() asm volatile("cp.async.commit_group;" ::: "memory")
#define CP_WAIT(N)  asm volatile("cp.async.wait_group %0;" :: "n"(N) : "memory")

__device__ __forceinline__ void ldm4(uint32_t* r, uint32_t addr) {
    asm volatile("ldmatrix.sync.aligned.m8n8.x4.shared.b16 {%0,%1,%2,%3}, [%4];"
        : "=r"(r[0]), "=r"(r[1]), "=r"(r[2]), "=r"(r[3]) : "r"(addr));
}
__device__ __forceinline__ void ldm4t(uint32_t* r, uint32_t addr) {
    asm volatile("ldmatrix.sync.aligned.m8n8.x4.trans.shared.b16 {%0,%1,%2,%3}, [%4];"
        : "=r"(r[0]), "=r"(r[1]), "=r"(r[2]), "=r"(r[3]) : "r"(addr));
}
__device__ __forceinline__ void mma16816(float* c, const uint32_t* a, const uint32_t* b) {
    asm volatile("mma.sync.aligned.m16n8k16.row.col.f32.bf16.bf16.f32 "
        "{%0,%1,%2,%3}, {%4,%5,%6,%7}, {%8,%9}, {%0,%1,%2,%3};"
        : "+f"(c[0]), "+f"(c[1]), "+f"(c[2]), "+f"(c[3])
        : "r"(a[0]), "r"(a[1]), "r"(a[2]), "r"(a[3]), "r"(b[0]), "r"(b[1]));
}
__device__ __forceinline__ uint32_t packbf2(float lo, float hi) {
    __nv_bfloat162 t = __floats2bfloat162_rn(lo, hi);
    return *(uint32_t*)&t;
}

// ---------------- pre-processing kernels ------------------------------------
__global__ void split_x_kernel(const float* __restrict__ X) {
    int i = blockIdx.x * blockDim.x + threadIdx.x;
    if (i < S_LEN * HID) {
        float x = X[i];
        __nv_bfloat16 h = __float2bfloat16(x);
        g_Xhi[i] = h;
        g_Xlo[i] = __float2bfloat16(x - __bfloat162float(h));
    }
}

__global__ void rope_table_kernel(const int* __restrict__ pid) {
    int idx = blockIdx.x * blockDim.x + threadIdx.x;
    if (idx < S_LEN * 64) {
        int s = idx >> 6, i = idx & 63;
        float inv_freq = expf(-(float)i * 0.21586735246819178f);
        float sv, cv;
        sincosf((float)pid[s] * inv_freq, &sv, &cv);
        g_rope_cos[idx] = cv;
        g_rope_sin[idx] = sv;
    }
}

__global__ void transpose_split(const float* __restrict__ W, int K, int N,
                                int dstSel, size_t dstOff) {
    __nv_bfloat16* Th = (dstSel ? g_Wo_hi : g_Wt_hi) + dstOff;
    __nv_bfloat16* Tl = (dstSel ? g_Wo_lo : g_Wt_lo) + dstOff;
    __shared__ float t[32][33];
    int n0 = blockIdx.x * 32, k0 = blockIdx.y * 32;
    int tx = threadIdx.x, ty = threadIdx.y;
#pragma unroll
    for (int i = 0; i < 32; i += 8)
        t[ty + i][tx] = W[(size_t)(k0 + ty + i) * N + n0 + tx];
    __syncthreads();
#pragma unroll
    for (int i = 0; i < 32; i += 8) {
        int n = n0 + ty + i, k = k0 + tx;
        float x = t[tx][ty + i];
        __nv_bfloat16 h = __float2bfloat16(x);
        Th[(size_t)n * K + k] = h;
        Tl[(size_t)n * K + k] = __float2bfloat16(x - __bfloat162float(h));
    }
}

// ---------------- HMMA bf16x3 GEMM: CTA 128x128, 4 warps, warp 64x64 --------
#define BK 32
#define TSTRIDE 40
#define TILE_BYTES (128 * TSTRIDE * 2)   // 10240
#define STAGE_BYTES (4 * TILE_BYTES)     // Ah | Al | Bh | Bl
#define GEMM_SMEM (2 * STAGE_BYTES)      // 81920

__device__ __forceinline__ void gemm_mainloop(
    const __nv_bfloat16* __restrict__ Ah, const __nv_bfloat16* __restrict__ Al,
    const __nv_bfloat16* __restrict__ Bh, const __nv_bfloat16* __restrict__ Bl,
    int Kd, int bm, int bnB, float acc[4][8][4], char* smem)
{
    const uint32_t sbase = smem_u32(smem);
    const int tid  = threadIdx.x;
    const int wid  = tid >> 5;          // 0..3
    const int lane = tid & 31;
    const int nch  = Kd >> 5;

    const int mw = (wid >> 1) * 64;
    const int nw = (wid & 1) * 64;

    const int rowA = mw + (lane & 15);
    const int colA = (lane >> 4) << 3;
    const int rowB = nw + (lane & 7) + ((lane >> 4) << 3);
    const int colB = ((lane >> 3) & 1) << 3;

#pragma unroll
    for (int mt = 0; mt < 4; ++mt)
#pragma unroll
        for (int nb = 0; nb < 8; ++nb)
#pragma unroll
            for (int q = 0; q < 4; ++q) acc[mt][nb][q] = 0.f;

    auto load_stage = [&](int ci, int buf) {
        const int k0 = ci << 5;
        const uint32_t st = sbase + buf * STAGE_BYTES;
#pragma unroll
        for (int it = 0; it < 16; ++it) {
            int u = tid + it * 128;
            int mat = u >> 9;            // 0 Ah, 1 Al, 2 Bh, 3 Bl
            int v = u & 511;
            int row = v >> 2;
            int seg = v & 3;
            const __nv_bfloat16* src;
            if (mat == 0)      src = Ah + (size_t)(bm + row) * Kd + k0 + seg * 8;
            else if (mat == 1) src = Al + (size_t)(bm + row) * Kd + k0 + seg * 8;
            else if (mat == 2) src = Bh + (size_t)(bnB + row) * Kd + k0 + seg * 8;
            else               src = Bl + (size_t)(bnB + row) * Kd + k0 + seg * 8;
            cp_async16(st + mat * TILE_BYTES + row * (TSTRIDE * 2) + seg * 16, src);
        }
        CP_COMMIT();
    };

    load_stage(0, 0);

    for (int i = 0; i < nch; ++i) {
        const int b = i & 1;
        if (i + 1 < nch) {
            load_stage(i + 1, b ^ 1);
            CP_WAIT(1);
        } else {
            CP_WAIT(0);
        }
        __syncthreads();

        const uint32_t sb = sbase + b * STAGE_BYTES;
#pragma unroll
        for (int kk = 0; kk < BK; kk += 16) {
            uint32_t fAh[4][4], fAl[4][4];
#pragma unroll
            for (int mt = 0; mt < 4; ++mt) {
                uint32_t ra = sb + ((rowA + mt * 16) * TSTRIDE + kk + colA) * 2;
                ldm4(fAh[mt], ra);
                ldm4(fAl[mt], ra + TILE_BYTES);
            }
#pragma unroll
            for (int np = 0; np < 4; ++np) {
                uint32_t fBh[4], fBl[4];
                uint32_t rb = sb + 2 * TILE_BYTES +
                              ((rowB + np * 16) * TSTRIDE + kk + colB) * 2;
                ldm4(fBh, rb);
                ldm4(fBl, rb + TILE_BYTES);
                // term-outer order: same acc reused only every 4 MMAs
#pragma unroll
                for (int half = 0; half < 2; ++half) {
                    int nb = np * 2 + half;
#pragma unroll
                    for (int mt = 0; mt < 4; ++mt)
                        mma16816(acc[mt][nb], fAh[mt], &fBh[half * 2]);
#pragma unroll
                    for (int mt = 0; mt < 4; ++mt)
                        mma16816(acc[mt][nb], fAh[mt], &fBl[half * 2]);
#pragma unroll
                    for (int mt = 0; mt < 4; ++mt)
                        mma16816(acc[mt][nb], fAl[mt], &fBh[half * 2]);
                }
            }
        }
        __syncthreads();
    }
}

// ---- QKV GEMM with fused RoPE (table) + bf16 hi/lo split epilogue ----------
__global__ __launch_bounds__(128) void qkv_gemm_kernel()
{
    extern __shared__ char smem[];
    const int bn = blockIdx.x * 128;        // column block = one head
    const int bm = blockIdx.y * 128;

    float acc[4][8][4];
    gemm_mainloop(g_Xhi, g_Xlo, g_Wt_hi, g_Wt_lo, HID, bm, bn, acc, smem);

    const int tid  = threadIdx.x;
    const int wid  = tid >> 5;
    const int lane = tid & 31;
    const int mw = (wid >> 1) * 64;
    const int nw = (wid & 1) * 64;

    float* sm = (float*)smem;
#pragma unroll
    for (int mt = 0; mt < 4; ++mt)
#pragma unroll
        for (int nb = 0; nb < 8; ++nb) {
            int r0 = mw + mt * 16 + (lane >> 2);
            int c0 = nw + nb * 8 + (lane & 3) * 2;
            *(float2*)&sm[r0 * 132 + c0]       = make_float2(acc[mt][nb][0], acc[mt][nb][1]);
            *(float2*)&sm[(r0 + 8) * 132 + c0] = make_float2(acc[mt][nb][2], acc[mt][nb][3]);
        }
    __syncthreads();

    const bool isV = (bn >= HID + 512);
    __nv_bfloat16 *Dh, *Dl;
    int ldd, cbase;
    if (bn < HID)            { Dh = g_Qh; Dl = g_Ql; ldd = HID;    cbase = bn; }
    else if (bn < HID + 512) { Dh = g_Kh; Dl = g_Kl; ldd = KV_DIM; cbase = bn - HID; }
    else                     { Dh = g_Vh; Dl = g_Vl; ldd = KV_DIM; cbase = bn - HID - 512; }

#pragma unroll
    for (int k = 0; k < 16; ++k) {
        int u = tid + k * 128;
        int row = u >> 4;
        int i0 = (u & 15) * 4;
        float y0[4], y1[4];
        if (!isV) {
            float4 cv = *(const float4*)&g_rope_cos[(size_t)(bm + row) * 64 + i0];
            float4 sv = *(const float4*)&g_rope_sin[(size_t)(bm + row) * 64 + i0];
            float c[4] = {cv.x, cv.y, cv.z, cv.w};
            float s[4] = {sv.x, sv.y, sv.z, sv.w};
#pragma unroll
            for (int j = 0; j < 4; ++j) {
                float x0 = sm[row * 132 + i0 + j];
                float x1 = sm[row * 132 + i0 + j + 64];
                y0[j] = x0 * c[j] - x1 * s[j];
                y1[j] = x1 * c[j] + x0 * s[j];
            }
        } else {
#pragma unroll
            for (int j = 0; j < 4; ++j) {
                y0[j] = sm[row * 132 + i0 + j];
                y1[j] = sm[row * 132 + i0 + j + 64];
            }
        }
        size_t d0 = (size_t)(bm + row) * ldd + cbase + i0;
        size_t d1 = d0 + 64;
        __nv_bfloat16 h[8]; float r[8];
#pragma unroll
        for (int j = 0; j < 4; ++j) {
            h[j]     = __float2bfloat16(y0[j]);
            r[j]     = y0[j] - __bfloat162float(h[j]);
            h[j + 4] = __float2bfloat16(y1[j]);
            r[j + 4] = y1[j] - __bfloat162float(h[j + 4]);
        }
        *(__nv_bfloat162*)&Dh[d0]     = __halves2bfloat162(h[0], h[1]);
        *(__nv_bfloat162*)&Dh[d0 + 2] = __halves2bfloat162(h[2], h[3]);
        *(__nv_bfloat162*)&Dh[d1]     = __halves2bfloat162(h[4], h[5]);
        *(__nv_bfloat162*)&Dh[d1 + 2] = __halves2bfloat162(h[6], h[7]);
        *(__nv_bfloat162*)&Dl[d0]     = __floats2bfloat162_rn(r[0], r[1]);
        *(__nv_bfloat162*)&Dl[d0 + 2] = __floats2bfloat162_rn(r[2], r[3]);
        *(__nv_bfloat162*)&Dl[d1]     = __floats2bfloat162_rn(r[4], r[5]);
        *(__nv_bfloat162*)&Dl[d1 + 2] = __floats2bfloat162_rn(r[6], r[7]);
    }
}

// ---- output projection GEMM (direct fp32 store epilogue) --------------------
__global__ __launch_bounds__(128) void out_gemm_kernel(float* __restrict__ out)
{
    extern __shared__ char smem[];
    const int bn = blockIdx.x * 128;
    const int bm = blockIdx.y * 128;

    float acc[4][8][4];
    gemm_mainloop(g_Ahi, g_Alo, g_Wo_hi, g_Wo_lo, HID, bm, bn, acc, smem);

    const int tid  = threadIdx.x;
    const int wid  = tid >> 5;
    const int lane = tid & 31;
    const int mw = (wid >> 1) * 64;
    const int nw = (wid & 1) * 64;

#pragma unroll
    for (int mt = 0; mt < 4; ++mt)
#pragma unroll
        for (int nb = 0; nb < 8; ++nb) {
            int r0 = bm + mw + mt * 16 + (lane >> 2);
            int c0 = bn + nw + nb * 8 + (lane & 3) * 2;
            float2 v0 = {acc[mt][nb][0], acc[mt][nb][1]};
            float2 v1 = {acc[mt][nb][2], acc[mt][nb][3]};
            *(float2*)(out + (size_t)r0 * HID + c0)       = v0;
            *(float2*)(out + (size_t)(r0 + 8) * HID + c0) = v1;
        }
}

// ---------------- HMMA bf16x3 flash attention (swizzled, 96 KB smem) ---------
// 6 tiles of [64 rows][128 cols bf16] = 256 B/row, 16 KB each.
// Swizzle: byte offset (r*256 + cb) ^ ((r&7)<<4)  -> conflict-free ldmatrix.
#define FSWZ(r, cb) ((((r) << 8) + (cb)) ^ (((r) & 7) << 4))
#define F_QH 0
#define F_QL 16384
#define F_KH 32768
#define F_KL 49152
#define F_VH 65536
#define F_VL 81920
#define FLASH_SMEM 98304

__global__ __launch_bounds__(128) void flash_kernel()
{
    const int qt  = (int)gridDim.x - 1 - (int)blockIdx.x;
    const int h   = blockIdx.y;
    const int kvh = h / (NH / NKV);

    extern __shared__ char fsm[];
    const uint32_t sb = smem_u32(fsm);

    const int tid  = threadIdx.x;
    const int w    = tid >> 5;
    const int lane = tid & 31;

    const int rowA   = w * 16 + (lane & 15);
    const int colA   = (lane >> 4) << 3;          // elems
    const int rowBo  = (lane & 7) + ((lane >> 4) << 3);
    const int colB   = ((lane >> 3) & 1) << 3;
    const int rowVt  = (lane & 7) + (((lane >> 3) & 1) << 3);
    const int colVt  = (lane >> 4) << 3;

    // load Q tile (hi/lo) with swizzle
    for (int f = tid; f < 1024; f += 128) {
        int r = f >> 4, cb = (f & 15) * 16;
        size_t g = (size_t)(qt * 64 + r) * HID + h * 128 + (f & 15) * 8;
        *(uint4*)(fsm + F_QH + FSWZ(r, cb)) = *(const uint4*)&g_Qh[g];
        *(uint4*)(fsm + F_QL + FSWZ(r, cb)) = *(const uint4*)&g_Ql[g];
    }

    float o[16][4];
#pragma unroll
    for (int nb = 0; nb < 16; ++nb)
#pragma unroll
        for (int q = 0; q < 4; ++q) o[nb][q] = 0.f;
    float m0 = -1e30f, m1 = -1e30f, l0 = 0.f, l1 = 0.f;

    const float SL = 0.08838834764831845f * 1.4426950408889634f;

    for (int kt = 0; kt <= qt; ++kt) {
        __syncthreads();
        for (int f = tid; f < 1024; f += 128) {
            int r = f >> 4, cb = (f & 15) * 16;
            size_t g = (size_t)(kt * 64 + r) * KV_DIM + kvh * 128 + (f & 15) * 8;
            uint32_t sw = FSWZ(r, cb);
            *(uint4*)(fsm + F_KH + sw) = *(const uint4*)&g_Kh[g];
            *(uint4*)(fsm + F_KL + sw) = *(const uint4*)&g_Kl[g];
            *(uint4*)(fsm + F_VH + sw) = *(const uint4*)&g_Vh[g];
            *(uint4*)(fsm + F_VL + sw) = *(const uint4*)&g_Vl[g];
        }
        __syncthreads();

        float s[8][4];
#pragma unroll
        for (int nb = 0; nb < 8; ++nb)
#pragma unroll
            for (int q = 0; q < 4; ++q) s[nb][q] = 0.f;

#pragma unroll
        for (int ks = 0; ks < 8; ++ks) {
            uint32_t qh[4], ql[4];
            uint32_t ca = ks * 32 + colA * 2;
            uint32_t swa = FSWZ(rowA, ca);
            ldm4(qh, sb + F_QH + swa);
            ldm4(ql, sb + F_QL + swa);
#pragma unroll
            for (int np = 0; np < 4; ++np) {
                uint32_t kh[4], kl[4];
                uint32_t cb = ks * 32 + colB * 2;
                uint32_t swb = FSWZ(np * 16 + rowBo, cb);
                ldm4(kh, sb + F_KH + swb);
                ldm4(kl, sb + F_KL + swb);
#pragma unroll
                for (int half = 0; half < 2; ++half) {
                    int nb = np * 2 + half;
                    mma16816(s[nb], qh, &kh[half * 2]);
                    mma16816(s[nb], qh, &kl[half * 2]);
                    mma16816(s[nb], ql, &kh[half * 2]);
                }
            }
        }

        const bool diag = (kt == qt);
        const int rl0 = w * 16 + (lane >> 2);
        const int rl1 = rl0 + 8;
        float mx0 = -1e30f, mx1 = -1e30f;
#pragma unroll
        for (int nb = 0; nb < 8; ++nb) {
            int c0 = nb * 8 + (lane & 3) * 2;
#pragma unroll
            for (int q = 0; q < 4; ++q) {
                float v = s[nb][q] * SL;
                if (diag) {
                    int col = c0 + (q & 1);
                    int row = (q < 2) ? rl0 : rl1;
                    if (col > row) v = -1e30f;
                }
                s[nb][q] = v;
            }
            mx0 = fmaxf(mx0, fmaxf(s[nb][0], s[nb][1]));
            mx1 = fmaxf(mx1, fmaxf(s[nb][2], s[nb][3]));
        }
        mx0 = fmaxf(mx0, __shfl_xor_sync(0xffffffffu, mx0, 1));
        mx0 = fmaxf(mx0, __shfl_xor_sync(0xffffffffu, mx0, 2));
        mx1 = fmaxf(mx1, __shfl_xor_sync(0xffffffffu, mx1, 1));
        mx1 = fmaxf(mx1, __shfl_xor_sync(0xffffffffu, mx1, 2));

        float mn0 = fmaxf(m0, mx0), mn1 = fmaxf(m1, mx1);
        float a0 = exp2f(m0 - mn0), a1 = exp2f(m1 - mn1);
        float ls0 = 0.f, ls1 = 0.f;
#pragma unroll
        for (int nb = 0; nb < 8; ++nb) {
            float p0 = exp2f(s[nb][0] - mn0);
            float p1 = exp2f(s[nb][1] - mn0);
            float p2 = exp2f(s[nb][2] - mn1);
            float p3 = exp2f(s[nb][3] - mn1);
            s[nb][0] = p0; s[nb][1] = p1; s[nb][2] = p2; s[nb][3] = p3;
            ls0 += p0 + p1;
            ls1 += p2 + p3;
        }
        ls0 += __shfl_xor_sync(0xffffffffu, ls0, 1);
        ls0 += __shfl_xor_sync(0xffffffffu, ls0, 2);
        ls1 += __shfl_xor_sync(0xffffffffu, ls1, 1);
        ls1 += __shfl_xor_sync(0xffffffffu, ls1, 2);
        l0 = l0 * a0 + ls0;
        l1 = l1 * a1 + ls1;
        m0 = mn0; m1 = mn1;

#pragma unroll
        for (int nb = 0; nb < 16; ++nb) {
            o[nb][0] *= a0; o[nb][1] *= a0;
            o[nb][2] *= a1; o[nb][3] *= a1;
        }

        uint32_t pah[4][4], pal[4][4];
#pragma unroll
        for (int kb = 0; kb < 4; ++kb) {
#pragma unroll
            for (int part = 0; part < 4; ++part) {
                int nb = 2 * kb + (part >> 1);
                float c0 = s[nb][(part & 1) * 2];
                float c1 = s[nb][(part & 1) * 2 + 1];
                __nv_bfloat162 hi2 = __floats2bfloat162_rn(c0, c1);
                pah[kb][part] = *(uint32_t*)&hi2;
                float r0 = c0 - __bfloat162float(hi2.x);
                float r1 = c1 - __bfloat162float(hi2.y);
                pal[kb][part] = packbf2(r0, r1);
            }
        }

#pragma unroll
        for (int kb = 0; kb < 4; ++kb) {
#pragma unroll
            for (int nv = 0; nv < 8; ++nv) {
                uint32_t vh[4], vl[4];
                uint32_t cv = nv * 32 + colVt * 2;
                uint32_t swv = FSWZ(kb * 16 + rowVt, cv);
                ldm4t(vh, sb + F_VH + swv);
                ldm4t(vl, sb + F_VL + swv);
#pragma unroll
                for (int half = 0; half < 2; ++half) {
                    int nbv = nv * 2 + half;
                    mma16816(o[nbv], pah[kb], &vh[half * 2]);
                    mma16816(o[nbv], pal[kb], &vh[half * 2]);
                    mma16816(o[nbv], pah[kb], &vl[half * 2]);
                }
            }
        }
    }

    const float inv0 = 1.0f / l0, inv1 = 1.0f / l1;
    const int r0 = qt * 64 + w * 16 + (lane >> 2);
    const int r1 = r0 + 8;
#pragma unroll
    for (int nb = 0; nb < 16; ++nb) {
        int c = h * 128 + nb * 8 + (lane & 3) * 2;
        float y0 = o[nb][0] * inv0, y1 = o[nb][1] * inv0;
        float y2 = o[nb][2] * inv1, y3 = o[nb][3] * inv1;
        __nv_bfloat162 h01 = __floats2bfloat162_rn(y0, y1);
        __nv_bfloat162 h23 = __floats2bfloat162_rn(y2, y3);
        *(__nv_bfloat162*)&g_Ahi[(size_t)r0 * HID + c] = h01;
        *(__nv_bfloat162*)&g_Ahi[(size_t)r1 * HID + c] = h23;
        __nv_bfloat162 l01 = __floats2bfloat162_rn(y0 - __bfloat162float(h01.x),
                                                   y1 - __bfloat162float(h01.y));
        __nv_bfloat162 l23 = __floats2bfloat162_rn(y2 - __bfloat162float(h23.x),
                                                   y3 - __bfloat162float(h23.y));
        *(__nv_bfloat162*)&g_Alo[(size_t)r0 * HID + c] = l01;
        *(__nv_bfloat162*)&g_Alo[(size_t)r1 * HID + c] = l23;
    }
}

// ---------------------------------------------------------------------------
extern "C" void kernel_launch(void* const* d_in, const int* in_sizes, int n_in,
                              void* d_out, int out_size)
{
    const float* X   = (const float*)d_in[0];
    const int*   pid = (const int*)  d_in[1];
    const float* Wq  = (const float*)d_in[2];
    const float* Wk  = (const float*)d_in[3];
    const float* Wv  = (const float*)d_in[4];
    const float* Wo  = (const float*)d_in[5];
    float* out = (float*)d_out;

    static int attr_set = 0;
    if (!attr_set) {
        cudaFuncSetAttribute(qkv_gemm_kernel, cudaFuncAttributeMaxDynamicSharedMemorySize, GEMM_SMEM);
        cudaFuncSetAttribute(out_gemm_kernel, cudaFuncAttributeMaxDynamicSharedMemorySize, GEMM_SMEM);
        cudaFuncSetAttribute(flash_kernel, cudaFuncAttributeMaxDynamicSharedMemorySize, FLASH_SMEM);
        attr_set = 1;
    }

    // launch order chosen so ncu (-s 5 -c 1) captures qkv_gemm_kernel (launch #6)
    split_x_kernel<<<(S_LEN * HID + 255) / 256, 256>>>(X);                          // 1
    transpose_split<<<dim3(HID / 32, HID / 32), dim3(32, 8)>>>(Wq, HID, HID, 0, 0); // 2
    transpose_split<<<dim3(KV_DIM / 32, HID / 32), dim3(32, 8)>>>(
        Wk, HID, KV_DIM, 0, (size_t)HID * HID);                                     // 3
    transpose_split<<<dim3(KV_DIM / 32, HID / 32), dim3(32, 8)>>>(
        Wv, HID, KV_DIM, 0, (size_t)(HID + 512) * HID);                             // 4
    rope_table_kernel<<<(S_LEN * 64 + 255) / 256, 256>>>(pid);                      // 5

    qkv_gemm_kernel<<<dim3(QKV_N / 128, S_LEN / 128), 128, GEMM_SMEM>>>();          // 6

    transpose_split<<<dim3(HID / 32, HID / 32), dim3(32, 8)>>>(Wo, HID, HID, 1, 0); // 7

    flash_kernel<<<dim3(32, 28), 128, FLASH_SMEM>>>();                              // 8

    out_gemm_kernel<<<dim3(HID / 128, S_LEN / 128), 128, GEMM_SMEM>>>(out);         // 9
}

// round 13
// speedup vs baseline: 1.0409x; 1.0409x over previous
#include <cuda_runtime.h>
#include <cuda_bf16.h>
#include <math.h>
#include <stdint.h>

#define S_LEN 2048
#define HID   3584
#define NH    28
#define NKV   4
#define HD    128
#define KV_DIM 512
#define QKV_N  4608   // 3584 + 512 + 512

// ---------------- scratch (__device__ globals; no allocs allowed) ----------
__device__ __nv_bfloat16 g_Xhi[S_LEN * HID];
__device__ __nv_bfloat16 g_Xlo[S_LEN * HID];
__device__ __nv_bfloat16 g_Ahi[S_LEN * HID];
__device__ __nv_bfloat16 g_Alo[S_LEN * HID];
__device__ __nv_bfloat16 g_Wt_hi[(size_t)QKV_N * HID];
__device__ __nv_bfloat16 g_Wt_lo[(size_t)QKV_N * HID];
__device__ __nv_bfloat16 g_Wo_hi[(size_t)HID * HID];
__device__ __nv_bfloat16 g_Wo_lo[(size_t)HID * HID];

__device__ __nv_bfloat16 g_Qh[S_LEN * HID];
__device__ __nv_bfloat16 g_Ql[S_LEN * HID];
__device__ __nv_bfloat16 g_Kh[S_LEN * KV_DIM];
__device__ __nv_bfloat16 g_Kl[S_LEN * KV_DIM];
__device__ __nv_bfloat16 g_Vh[S_LEN * KV_DIM];
__device__ __nv_bfloat16 g_Vl[S_LEN * KV_DIM];

__device__ float g_rope_cos[S_LEN * 64];
__device__ float g_rope_sin[S_LEN * 64];

// ---------------- PTX helpers (baseline PTX only) ---------------------------
__device__ __forceinline__ uint32_t smem_u32(const void* p) {
    uint32_t a;
    asm("{ .reg .u64 t; cvta.to.shared.u64 t, %1; cvt.u32.u64 %0, t; }" : "=r"(a) : "l"(p));
    return a;
}
__device__ __forceinline__ void cp_async16(uint32_t dst, const void* src) {
    asm volatile("cp.async.cg.shared.global [%0], [%1], 16;" :: "r"(dst), "l"(src));
}
#define CP_COMMIT() asm volatile("cp.async.commit_group;" ::: "memory")
#define CP_WAIT(N)  asm volatile("cp.async.wait_group %0;" :: "n"(N) : "memory")

__device__ __forceinline__ void ldm4(uint32_t* r, uint32_t addr) {
    asm volatile("ldmatrix.sync.aligned.m8n8.x4.shared.b16 {%0,%1,%2,%3}, [%4];"
        : "=r"(r[0]), "=r"(r[1]), "=r"(r[2]), "=r"(r[3]) : "r"(addr));
}
__device__ __forceinline__ void ldm4t(uint32_t* r, uint32_t addr) {
    asm volatile("ldmatrix.sync.aligned.m8n8.x4.trans.shared.b16 {%0,%1,%2,%3}, [%4];"
        : "=r"(r[0]), "=r"(r[1]), "=r"(r[2]), "=r"(r[3]) : "r"(addr));
}
__device__ __forceinline__ void mma16816(float* c, const uint32_t* a, const uint32_t* b) {
    asm volatile("mma.sync.aligned.m16n8k16.row.col.f32.bf16.bf16.f32 "
        "{%0,%1,%2,%3}, {%4,%5,%6,%7}, {%8,%9}, {%0,%1,%2,%3};"
        : "+f"(c[0]), "+f"(c[1]), "+f"(c[2]), "+f"(c[3])
        : "r"(a[0]), "r"(a[1]), "r"(a[2]), "r"(a[3]), "r"(b[0]), "r"(b[1]));
}
__device__ __forceinline__ uint32_t packbf2(float lo, float hi) {
    __nv_bfloat162 t = __floats2bfloat162_rn(lo, hi);
    return *(uint32_t*)&t;
}

// ---------------- pre-processing kernels ------------------------------------
__global__ void split_x_kernel(const float* __restrict__ X) {
    int i = blockIdx.x * blockDim.x + threadIdx.x;
    if (i < S_LEN * HID) {
        float x = X[i];
        __nv_bfloat16 h = __float2bfloat16(x);
        g_Xhi[i] = h;
        g_Xlo[i] = __float2bfloat16(x - __bfloat162float(h));
    }
}

__global__ void rope_table_kernel(const int* __restrict__ pid) {
    int idx = blockIdx.x * blockDim.x + threadIdx.x;
    if (idx < S_LEN * 64) {
        int s = idx >> 6, i = idx & 63;
        float inv_freq = expf(-(float)i * 0.21586735246819178f);
        float sv, cv;
        sincosf((float)pid[s] * inv_freq, &sv, &cv);
        g_rope_cos[idx] = cv;
        g_rope_sin[idx] = sv;
    }
}

__global__ void transpose_split(const float* __restrict__ W, int K, int N,
                                int dstSel, size_t dstOff) {
    __nv_bfloat16* Th = (dstSel ? g_Wo_hi : g_Wt_hi) + dstOff;
    __nv_bfloat16* Tl = (dstSel ? g_Wo_lo : g_Wt_lo) + dstOff;
    __shared__ float t[32][33];
    int n0 = blockIdx.x * 32, k0 = blockIdx.y * 32;
    int tx = threadIdx.x, ty = threadIdx.y;
#pragma unroll
    for (int i = 0; i < 32; i += 8)
        t[ty + i][tx] = W[(size_t)(k0 + ty + i) * N + n0 + tx];
    __syncthreads();
#pragma unroll
    for (int i = 0; i < 32; i += 8) {
        int n = n0 + ty + i, k = k0 + tx;
        float x = t[tx][ty + i];
        __nv_bfloat16 h = __float2bfloat16(x);
        Th[(size_t)n * K + k] = h;
        Tl[(size_t)n * K + k] = __float2bfloat16(x - __bfloat162float(h));
    }
}

// ---------------- HMMA bf16x3 GEMM: CTA 128x128, 4 warps, warp 64x64 --------
// 3-stage pipeline, one __syncthreads per chunk, XOR-swizzled unpadded tiles.
// Tile: 128 rows x 32 bf16 = 64 B/row = 4 x 16B units; swizzle u' = u ^ ((r>>1)&3)
#define GSWZ(r, u) (((r) << 6) + ((((u) ^ ((r) >> 1)) & 3) << 4))
#define GTILE 8192
#define GSTG  (4 * GTILE)          // Ah | Al | Bh | Bl = 32768
#define GEMM_SMEM (3 * GSTG)       // 98304 (3 stages) -> 2 CTAs/SM

__device__ __forceinline__ void gemm_mainloop(
    const __nv_bfloat16* __restrict__ Ah, const __nv_bfloat16* __restrict__ Al,
    const __nv_bfloat16* __restrict__ Bh, const __nv_bfloat16* __restrict__ Bl,
    int Kd, int bm, int bnB, float acc[4][8][4], char* smem)
{
    const uint32_t sbase = smem_u32(smem);
    const int tid  = threadIdx.x;
    const int wid  = tid >> 5;          // 0..3
    const int lane = tid & 31;
    const int nch  = Kd >> 5;

    const int mw = (wid >> 1) * 64;
    const int nw = (wid & 1) * 64;

    const int rowA = mw + (lane & 15);
    const int uA   = (lane >> 4) & 1;            // 16B unit within kk half
    const int rowB = nw + (lane & 7) + ((lane >> 4) << 3);
    const int uB   = (lane >> 3) & 1;

#pragma unroll
    for (int mt = 0; mt < 4; ++mt)
#pragma unroll
        for (int nb = 0; nb < 8; ++nb)
#pragma unroll
            for (int q = 0; q < 4; ++q) acc[mt][nb][q] = 0.f;

    // stage loader: 2048 x 16B segments, 16 per thread (128 threads)
    auto load_stage = [&](int ci, int slot) {
        const int k0 = ci << 5;
        const uint32_t st = sbase + slot * GSTG;
#pragma unroll
        for (int it = 0; it < 16; ++it) {
            int u = tid + it * 128;
            int mat = u >> 9;            // 0 Ah, 1 Al, 2 Bh, 3 Bl
            int v = u & 511;
            int row = v >> 2;
            int seg = v & 3;
            const __nv_bfloat16* src;
            if (mat == 0)      src = Ah + (size_t)(bm + row) * Kd + k0 + seg * 8;
            else if (mat == 1) src = Al + (size_t)(bm + row) * Kd + k0 + seg * 8;
            else if (mat == 2) src = Bh + (size_t)(bnB + row) * Kd + k0 + seg * 8;
            else               src = Bl + (size_t)(bnB + row) * Kd + k0 + seg * 8;
            cp_async16(st + mat * GTILE + GSWZ(row, seg), src);
        }
        CP_COMMIT();
    };

    load_stage(0, 0);
    load_stage(1, 1);

    int slot = 0;
    for (int i = 0; i < nch; ++i) {
        if (i + 1 < nch) { CP_WAIT(1); } else { CP_WAIT(0); }
        __syncthreads();                       // stage i published; stage (i+2)%3 free
        if (i + 2 < nch) load_stage(i + 2, (slot + 2) % 3);

        const uint32_t sb = sbase + slot * GSTG;
#pragma unroll
        for (int kk2 = 0; kk2 < 2; ++kk2) {    // kk = kk2*16
            uint32_t fAh[4][4], fAl[4][4];
#pragma unroll
            for (int mt = 0; mt < 4; ++mt) {
                uint32_t sw = GSWZ(rowA + mt * 16, kk2 * 2 + uA);
                ldm4(fAh[mt], sb + sw);
                ldm4(fAl[mt], sb + GTILE + sw);
            }
#pragma unroll
            for (int np = 0; np < 4; ++np) {
                uint32_t fBh[4], fBl[4];
                uint32_t sw = GSWZ(np * 16 + rowB, kk2 * 2 + uB);
                ldm4(fBh, sb + 2 * GTILE + sw);
                ldm4(fBl, sb + 3 * GTILE + sw);
#pragma unroll
                for (int half = 0; half < 2; ++half) {
                    int nb = np * 2 + half;
#pragma unroll
                    for (int mt = 0; mt < 4; ++mt)
                        mma16816(acc[mt][nb], fAh[mt], &fBh[half * 2]);
#pragma unroll
                    for (int mt = 0; mt < 4; ++mt)
                        mma16816(acc[mt][nb], fAh[mt], &fBl[half * 2]);
#pragma unroll
                    for (int mt = 0; mt < 4; ++mt)
                        mma16816(acc[mt][nb], fAl[mt], &fBh[half * 2]);
                }
            }
        }
        slot = (slot + 1) % 3;
    }
    __syncthreads();   // all warps done with smem before epilogue reuse
}

// ---- QKV GEMM with fused RoPE (table) + bf16 hi/lo split epilogue ----------
__global__ __launch_bounds__(128) void qkv_gemm_kernel()
{
    extern __shared__ char smem[];
    const int bn = blockIdx.x * 128;        // column block = one head
    const int bm = blockIdx.y * 128;

    float acc[4][8][4];
    gemm_mainloop(g_Xhi, g_Xlo, g_Wt_hi, g_Wt_lo, HID, bm, bn, acc, smem);

    const int tid  = threadIdx.x;
    const int wid  = tid >> 5;
    const int lane = tid & 31;
    const int mw = (wid >> 1) * 64;
    const int nw = (wid & 1) * 64;

    float* sm = (float*)smem;
#pragma unroll
    for (int mt = 0; mt < 4; ++mt)
#pragma unroll
        for (int nb = 0; nb < 8; ++nb) {
            int r0 = mw + mt * 16 + (lane >> 2);
            int c0 = nw + nb * 8 + (lane & 3) * 2;
            *(float2*)&sm[r0 * 132 + c0]       = make_float2(acc[mt][nb][0], acc[mt][nb][1]);
            *(float2*)&sm[(r0 + 8) * 132 + c0] = make_float2(acc[mt][nb][2], acc[mt][nb][3]);
        }
    __syncthreads();

    const bool isV = (bn >= HID + 512);
    __nv_bfloat16 *Dh, *Dl;
    int ldd, cbase;
    if (bn < HID)            { Dh = g_Qh; Dl = g_Ql; ldd = HID;    cbase = bn; }
    else if (bn < HID + 512) { Dh = g_Kh; Dl = g_Kl; ldd = KV_DIM; cbase = bn - HID; }
    else                     { Dh = g_Vh; Dl = g_Vl; ldd = KV_DIM; cbase = bn - HID - 512; }

#pragma unroll
    for (int k = 0; k < 16; ++k) {
        int u = tid + k * 128;
        int row = u >> 4;
        int i0 = (u & 15) * 4;
        float y0[4], y1[4];
        if (!isV) {
            float4 cv = *(const float4*)&g_rope_cos[(size_t)(bm + row) * 64 + i0];
            float4 sv = *(const float4*)&g_rope_sin[(size_t)(bm + row) * 64 + i0];
            float c[4] = {cv.x, cv.y, cv.z, cv.w};
            float s[4] = {sv.x, sv.y, sv.z, sv.w};
#pragma unroll
            for (int j = 0; j < 4; ++j) {
                float x0 = sm[row * 132 + i0 + j];
                float x1 = sm[row * 132 + i0 + j + 64];
                y0[j] = x0 * c[j] - x1 * s[j];
                y1[j] = x1 * c[j] + x0 * s[j];
            }
        } else {
#pragma unroll
            for (int j = 0; j < 4; ++j) {
                y0[j] = sm[row * 132 + i0 + j];
                y1[j] = sm[row * 132 + i0 + j + 64];
            }
        }
        size_t d0 = (size_t)(bm + row) * ldd + cbase + i0;
        size_t d1 = d0 + 64;
        __nv_bfloat16 h[8]; float r[8];
#pragma unroll
        for (int j = 0; j < 4; ++j) {
            h[j]     = __float2bfloat16(y0[j]);
            r[j]     = y0[j] - __bfloat162float(h[j]);
            h[j + 4] = __float2bfloat16(y1[j]);
            r[j + 4] = y1[j] - __bfloat162float(h[j + 4]);
        }
        *(__nv_bfloat162*)&Dh[d0]     = __halves2bfloat162(h[0], h[1]);
        *(__nv_bfloat162*)&Dh[d0 + 2] = __halves2bfloat162(h[2], h[3]);
        *(__nv_bfloat162*)&Dh[d1]     = __halves2bfloat162(h[4], h[5]);
        *(__nv_bfloat162*)&Dh[d1 + 2] = __halves2bfloat162(h[6], h[7]);
        *(__nv_bfloat162*)&Dl[d0]     = __floats2bfloat162_rn(r[0], r[1]);
        *(__nv_bfloat162*)&Dl[d0 + 2] = __floats2bfloat162_rn(r[2], r[3]);
        *(__nv_bfloat162*)&Dl[d1]     = __floats2bfloat162_rn(r[4], r[5]);
        *(__nv_bfloat162*)&Dl[d1 + 2] = __floats2bfloat162_rn(r[6], r[7]);
    }
}

// ---- output projection GEMM (direct fp32 store epilogue) --------------------
__global__ __launch_bounds__(128) void out_gemm_kernel(float* __restrict__ out)
{
    extern __shared__ char smem[];
    const int bn = blockIdx.x * 128;
    const int bm = blockIdx.y * 128;

    float acc[4][8][4];
    gemm_mainloop(g_Ahi, g_Alo, g_Wo_hi, g_Wo_lo, HID, bm, bn, acc, smem);

    const int tid  = threadIdx.x;
    const int wid  = tid >> 5;
    const int lane = tid & 31;
    const int mw = (wid >> 1) * 64;
    const int nw = (wid & 1) * 64;

#pragma unroll
    for (int mt = 0; mt < 4; ++mt)
#pragma unroll
        for (int nb = 0; nb < 8; ++nb) {
            int r0 = bm + mw + mt * 16 + (lane >> 2);
            int c0 = bn + nw + nb * 8 + (lane & 3) * 2;
            float2 v0 = {acc[mt][nb][0], acc[mt][nb][1]};
            float2 v1 = {acc[mt][nb][2], acc[mt][nb][3]};
            *(float2*)(out + (size_t)r0 * HID + c0)       = v0;
            *(float2*)(out + (size_t)(r0 + 8) * HID + c0) = v1;
        }
}

// ---------------- HMMA bf16x3 flash attention (swizzled, 96 KB smem) ---------
#define FSWZ(r, cb) ((((r) << 8) + (cb)) ^ (((r) & 7) << 4))
#define F_QH 0
#define F_QL 16384
#define F_KH 32768
#define F_KL 49152
#define F_VH 65536
#define F_VL 81920
#define FLASH_SMEM 98304

__global__ __launch_bounds__(128) void flash_kernel()
{
    const int qt  = (int)gridDim.x - 1 - (int)blockIdx.x;
    const int h   = blockIdx.y;
    const int kvh = h / (NH / NKV);

    extern __shared__ char fsm[];
    const uint32_t sb = smem_u32(fsm);

    const int tid  = threadIdx.x;
    const int w    = tid >> 5;
    const int lane = tid & 31;

    const int rowA   = w * 16 + (lane & 15);
    const int colA   = (lane >> 4) << 3;
    const int rowBo  = (lane & 7) + ((lane >> 4) << 3);
    const int colB   = ((lane >> 3) & 1) << 3;
    const int rowVt  = (lane & 7) + (((lane >> 3) & 1) << 3);
    const int colVt  = (lane >> 4) << 3;

    for (int f = tid; f < 1024; f += 128) {
        int r = f >> 4, cb = (f & 15) * 16;
        size_t g = (size_t)(qt * 64 + r) * HID + h * 128 + (f & 15) * 8;
        *(uint4*)(fsm + F_QH + FSWZ(r, cb)) = *(const uint4*)&g_Qh[g];
        *(uint4*)(fsm + F_QL + FSWZ(r, cb)) = *(const uint4*)&g_Ql[g];
    }

    float o[16][4];
#pragma unroll
    for (int nb = 0; nb < 16; ++nb)
#pragma unroll
        for (int q = 0; q < 4; ++q) o[nb][q] = 0.f;
    float m0 = -1e30f, m1 = -1e30f, l0 = 0.f, l1 = 0.f;

    const float SL = 0.08838834764831845f * 1.4426950408889634f;

    for (int kt = 0; kt <= qt; ++kt) {
        __syncthreads();
        for (int f = tid; f < 1024; f += 128) {
            int r = f >> 4, cb = (f & 15) * 16;
            size_t g = (size_t)(kt * 64 + r) * KV_DIM + kvh * 128 + (f & 15) * 8;
            uint32_t sw = FSWZ(r, cb);
            *(uint4*)(fsm + F_KH + sw) = *(const uint4*)&g_Kh[g];
            *(uint4*)(fsm + F_KL + sw) = *(const uint4*)&g_Kl[g];
            *(uint4*)(fsm + F_VH + sw) = *(const uint4*)&g_Vh[g];
            *(uint4*)(fsm + F_VL + sw) = *(const uint4*)&g_Vl[g];
        }
        __syncthreads();

        float s[8][4];
#pragma unroll
        for (int nb = 0; nb < 8; ++nb)
#pragma unroll
            for (int q = 0; q < 4; ++q) s[nb][q] = 0.f;

#pragma unroll
        for (int ks = 0; ks < 8; ++ks) {
            uint32_t qh[4], ql[4];
            uint32_t swa = FSWZ(rowA, ks * 32 + colA * 2);
            ldm4(qh, sb + F_QH + swa);
            ldm4(ql, sb + F_QL + swa);
#pragma unroll
            for (int np = 0; np < 4; ++np) {
                uint32_t kh[4], kl[4];
                uint32_t swb = FSWZ(np * 16 + rowBo, ks * 32 + colB * 2);
                ldm4(kh, sb + F_KH + swb);
                ldm4(kl, sb + F_KL + swb);
#pragma unroll
                for (int half = 0; half < 2; ++half) {
                    int nb = np * 2 + half;
                    mma16816(s[nb], qh, &kh[half * 2]);
                    mma16816(s[nb], qh, &kl[half * 2]);
                    mma16816(s[nb], ql, &kh[half * 2]);
                }
            }
        }

        const bool diag = (kt == qt);
        const int rl0 = w * 16 + (lane >> 2);
        const int rl1 = rl0 + 8;
        float mx0 = -1e30f, mx1 = -1e30f;
#pragma unroll
        for (int nb = 0; nb < 8; ++nb) {
            int c0 = nb * 8 + (lane & 3) * 2;
#pragma unroll
            for (int q = 0; q < 4; ++q) {
                float v = s[nb][q] * SL;
                if (diag) {
                    int col = c0 + (q & 1);
                    int row = (q < 2) ? rl0 : rl1;
                    if (col > row) v = -1e30f;
                }
                s[nb][q] = v;
            }
            mx0 = fmaxf(mx0, fmaxf(s[nb][0], s[nb][1]));
            mx1 = fmaxf(mx1, fmaxf(s[nb][2], s[nb][3]));
        }
        mx0 = fmaxf(mx0, __shfl_xor_sync(0xffffffffu, mx0, 1));
        mx0 = fmaxf(mx0, __shfl_xor_sync(0xffffffffu, mx0, 2));
        mx1 = fmaxf(mx1, __shfl_xor_sync(0xffffffffu, mx1, 1));
        mx1 = fmaxf(mx1, __shfl_xor_sync(0xffffffffu, mx1, 2));

        float mn0 = fmaxf(m0, mx0), mn1 = fmaxf(m1, mx1);
        float a0 = exp2f(m0 - mn0), a1 = exp2f(m1 - mn1);
        float ls0 = 0.f, ls1 = 0.f;
#pragma unroll
        for (int nb = 0; nb < 8; ++nb) {
            float p0 = exp2f(s[nb][0] - mn0);
            float p1 = exp2f(s[nb][1] - mn0);
            float p2 = exp2f(s[nb][2] - mn1);
            float p3 = exp2f(s[nb][3] - mn1);
            s[nb][0] = p0; s[nb][1] = p1; s[nb][2] = p2; s[nb][3] = p3;
            ls0 += p0 + p1;
            ls1 += p2 + p3;
        }
        ls0 += __shfl_xor_sync(0xffffffffu, ls0, 1);
        ls0 += __shfl_xor_sync(0xffffffffu, ls0, 2);
        ls1 += __shfl_xor_sync(0xffffffffu, ls1, 1);
        ls1 += __shfl_xor_sync(0xffffffffu, ls1, 2);
        l0 = l0 * a0 + ls0;
        l1 = l1 * a1 + ls1;
        m0 = mn0; m1 = mn1;

#pragma unroll
        for (int nb = 0; nb < 16; ++nb) {
            o[nb][0] *= a0; o[nb][1] *= a0;
            o[nb][2] *= a1; o[nb][3] *= a1;
        }

        uint32_t pah[4][4], pal[4][4];
#pragma unroll
        for (int kb = 0; kb < 4; ++kb) {
#pragma unroll
            for (int part = 0; part < 4; ++part) {
                int nb = 2 * kb + (part >> 1);
                float c0 = s[nb][(part & 1) * 2];
                float c1 = s[nb][(part & 1) * 2 + 1];
                __nv_bfloat162 hi2 = __floats2bfloat162_rn(c0, c1);
                pah[kb][part] = *(uint32_t*)&hi2;
                float r0 = c0 - __bfloat162float(hi2.x);
                float r1 = c1 - __bfloat162float(hi2.y);
                pal[kb][part] = packbf2(r0, r1);
            }
        }

#pragma unroll
        for (int kb = 0; kb < 4; ++kb) {
#pragma unroll
            for (int nv = 0; nv < 8; ++nv) {
                uint32_t vh[4], vl[4];
                uint32_t swv = FSWZ(kb * 16 + rowVt, nv * 32 + colVt * 2);
                ldm4t(vh, sb + F_VH + swv);
                ldm4t(vl, sb + F_VL + swv);
#pragma unroll
                for (int half = 0; half < 2; ++half) {
                    int nbv = nv * 2 + half;
                    mma16816(o[nbv], pah[kb], &vh[half * 2]);
                    mma16816(o[nbv], pal[kb], &vh[half * 2]);
                    mma16816(o[nbv], pah[kb], &vl[half * 2]);
                }
            }
        }
    }

    const float inv0 = 1.0f / l0, inv1 = 1.0f / l1;
    const int r0 = qt * 64 + w * 16 + (lane >> 2);
    const int r1 = r0 + 8;
#pragma unroll
    for (int nb = 0; nb < 16; ++nb) {
        int c = h * 128 + nb * 8 + (lane & 3) * 2;
        float y0 = o[nb][0] * inv0, y1 = o[nb][1] * inv0;
        float y2 = o[nb][2] * inv1, y3 = o[nb][3] * inv1;
        __nv_bfloat162 h01 = __floats2bfloat162_rn(y0, y1);
        __nv_bfloat162 h23 = __floats2bfloat162_rn(y2, y3);
        *(__nv_bfloat162*)&g_Ahi[(size_t)r0 * HID + c] = h01;
        *(__nv_bfloat162*)&g_Ahi[(size_t)r1 * HID + c] = h23;
        __nv_bfloat162 l01 = __floats2bfloat162_rn(y0 - __bfloat162float(h01.x),
                                                   y1 - __bfloat162float(h01.y));
        __nv_bfloat162 l23 = __floats2bfloat162_rn(y2 - __bfloat162float(h23.x),
                                                   y3 - __bfloat162float(h23.y));
        *(__nv_bfloat162*)&g_Alo[(size_t)r0 * HID + c] = l01;
        *(__nv_bfloat162*)&g_Alo[(size_t)r1 * HID + c] = l23;
    }
}

// ---------------------------------------------------------------------------
extern "C" void kernel_launch(void* const* d_in, const int* in_sizes, int n_in,
                              void* d_out, int out_size)
{
    const float* X   = (const float*)d_in[0];
    const int*   pid = (const int*)  d_in[1];
    const float* Wq  = (const float*)d_in[2];
    const float* Wk  = (const float*)d_in[3];
    const float* Wv  = (const float*)d_in[4];
    const float* Wo  = (const float*)d_in[5];
    float* out = (float*)d_out;

    static int attr_set = 0;
    if (!attr_set) {
        cudaFuncSetAttribute(qkv_gemm_kernel, cudaFuncAttributeMaxDynamicSharedMemorySize, GEMM_SMEM);
        cudaFuncSetAttribute(out_gemm_kernel, cudaFuncAttributeMaxDynamicSharedMemorySize, GEMM_SMEM);
        cudaFuncSetAttribute(flash_kernel, cudaFuncAttributeMaxDynamicSharedMemorySize, FLASH_SMEM);
        attr_set = 1;
    }

    split_x_kernel<<<(S_LEN * HID + 255) / 256, 256>>>(X);
    transpose_split<<<dim3(HID / 32, HID / 32), dim3(32, 8)>>>(Wq, HID, HID, 0, 0);
    transpose_split<<<dim3(KV_DIM / 32, HID / 32), dim3(32, 8)>>>(
        Wk, HID, KV_DIM, 0, (size_t)HID * HID);
    transpose_split<<<dim3(KV_DIM / 32, HID / 32), dim3(32, 8)>>>(
        Wv, HID, KV_DIM, 0, (size_t)(HID + 512) * HID);
    rope_table_kernel<<<(S_LEN * 64 + 255) / 256, 256>>>(pid);

    qkv_gemm_kernel<<<dim3(QKV_N / 128, S_LEN / 128), 128, GEMM_SMEM>>>();

    transpose_split<<<dim3(HID / 32, HID / 32), dim3(32, 8)>>>(Wo, HID, HID, 1, 0);

    flash_kernel<<<dim3(32, 28), 128, FLASH_SMEM>>>();

    out_gemm_kernel<<<dim3(HID / 128, S_LEN / 128), 128, GEMM_SMEM>>>(out);
}

// round 14
// speedup vs baseline: 1.3912x; 1.3366x over previous
#include <cuda_runtime.h>
#include <cuda_bf16.h>
#include <cuda_fp16.h>
#include <math.h>
#include <stdint.h>

#define S_LEN 2048
#define HID   3584
#define NH    28
#define NKV   4
#define HD    128
#define KV_DIM 512
#define QKV_N  4608   // 3584 + 512 + 512

// ---------------- scratch (__device__ globals; no allocs allowed) ----------
__device__ __half g_Xhi[S_LEN * HID];          // X split hi/lo (fp16)
__device__ __half g_Xlo[S_LEN * HID];
__device__ __half g_Ahi[S_LEN * HID];          // attention out split hi/lo (fp16)
__device__ __half g_Alo[S_LEN * HID];
__device__ __half g_Wt_h[(size_t)QKV_N * HID]; // [n][k] QKV weights, single fp16
__device__ __half g_Wo_h[(size_t)HID * HID];   // [n][k] Wo, single fp16

__device__ __nv_bfloat16 g_Qh[S_LEN * HID];    // flash inputs stay bf16 hi/lo
__device__ __nv_bfloat16 g_Ql[S_LEN * HID];
__device__ __nv_bfloat16 g_Kh[S_LEN * KV_DIM];
__device__ __nv_bfloat16 g_Kl[S_LEN * KV_DIM];
__device__ __nv_bfloat16 g_Vh[S_LEN * KV_DIM];
__device__ __nv_bfloat16 g_Vl[S_LEN * KV_DIM];

__device__ float g_rope_cos[S_LEN * 64];
__device__ float g_rope_sin[S_LEN * 64];

// ---------------- PTX helpers (baseline PTX only) ---------------------------
__device__ __forceinline__ uint32_t smem_u32(const void* p) {
    uint32_t a;
    asm("{ .reg .u64 t; cvta.to.shared.u64 t, %1; cvt.u32.u64 %0, t; }" : "=r"(a) : "l"(p));
    return a;
}
__device__ __forceinline__ void cp_async16(uint32_t dst, const void* src) {
    asm volatile("cp.async.cg.shared.global [%0], [%1], 16;" :: "r"(dst), "l"(src));
}
#define CP_COMMIT() asm volatile("cp.async.commit_group;" ::: "memory")
#define CP_WAIT(N)  asm volatile("cp.async.wait_group %0;" :: "n"(N) : "memory")

__device__ __forceinline__ void ldm4(uint32_t* r, uint32_t addr) {
    asm volatile("ldmatrix.sync.aligned.m8n8.x4.shared.b16 {%0,%1,%2,%3}, [%4];"
        : "=r"(r[0]), "=r"(r[1]), "=r"(r[2]), "=r"(r[3]) : "r"(addr));
}
__device__ __forceinline__ void ldm4t(uint32_t* r, uint32_t addr) {
    asm volatile("ldmatrix.sync.aligned.m8n8.x4.trans.shared.b16 {%0,%1,%2,%3}, [%4];"
        : "=r"(r[0]), "=r"(r[1]), "=r"(r[2]), "=r"(r[3]) : "r"(addr));
}
// bf16 MMA (flash)
__device__ __forceinline__ void mma16816(float* c, const uint32_t* a, const uint32_t* b) {
    asm volatile("mma.sync.aligned.m16n8k16.row.col.f32.bf16.bf16.f32 "
        "{%0,%1,%2,%3}, {%4,%5,%6,%7}, {%8,%9}, {%0,%1,%2,%3};"
        : "+f"(c[0]), "+f"(c[1]), "+f"(c[2]), "+f"(c[3])
        : "r"(a[0]), "r"(a[1]), "r"(a[2]), "r"(a[3]), "r"(b[0]), "r"(b[1]));
}
// fp16 MMA (projections)
__device__ __forceinline__ void mma16816h(float* c, const uint32_t* a, const uint32_t* b) {
    asm volatile("mma.sync.aligned.m16n8k16.row.col.f32.f16.f16.f32 "
        "{%0,%1,%2,%3}, {%4,%5,%6,%7}, {%8,%9}, {%0,%1,%2,%3};"
        : "+f"(c[0]), "+f"(c[1]), "+f"(c[2]), "+f"(c[3])
        : "r"(a[0]), "r"(a[1]), "r"(a[2]), "r"(a[3]), "r"(b[0]), "r"(b[1]));
}
__device__ __forceinline__ uint32_t packbf2(float lo, float hi) {
    __nv_bfloat162 t = __floats2bfloat162_rn(lo, hi);
    return *(uint32_t*)&t;
}

// ---------------- pre-processing kernels ------------------------------------
__global__ void split_x_kernel(const float* __restrict__ X) {
    int i = blockIdx.x * blockDim.x + threadIdx.x;
    if (i < S_LEN * HID) {
        float x = X[i];
        __half h = __float2half_rn(x);
        g_Xhi[i] = h;
        g_Xlo[i] = __float2half_rn(x - __half2float(h));
    }
}

__global__ void rope_table_kernel(const int* __restrict__ pid) {
    int idx = blockIdx.x * blockDim.x + threadIdx.x;
    if (idx < S_LEN * 64) {
        int s = idx >> 6, i = idx & 63;
        float inv_freq = expf(-(float)i * 0.21586735246819178f);
        float sv, cv;
        sincosf((float)pid[s] * inv_freq, &sv, &cv);
        g_rope_cos[idx] = cv;
        g_rope_sin[idx] = sv;
    }
}

// W[K][N] fp32 -> dst[n][k] single fp16
__global__ void transpose_h(const float* __restrict__ W, int K, int N,
                            int dstSel, size_t dstOff) {
    __half* Th = (dstSel ? g_Wo_h : g_Wt_h) + dstOff;
    __shared__ float t[32][33];
    int n0 = blockIdx.x * 32, k0 = blockIdx.y * 32;
    int tx = threadIdx.x, ty = threadIdx.y;
#pragma unroll
    for (int i = 0; i < 32; i += 8)
        t[ty + i][tx] = W[(size_t)(k0 + ty + i) * N + n0 + tx];
    __syncthreads();
#pragma unroll
    for (int i = 0; i < 32; i += 8) {
        int n = n0 + ty + i, k = k0 + tx;
        Th[(size_t)n * K + k] = __float2half_rn(t[tx][ty + i]);
    }
}

// ---------------- fp16x2 HMMA GEMM: CTA 128x128, 4 warps, warp 64x64 --------
// 3-stage pipeline, one __syncthreads per chunk, XOR-swizzled unpadded tiles.
// Tiles per stage: A_hi | A_lo | B  (3 x 8192 = 24576 B)
#define GSWZ(r, u) (((r) << 6) + ((((u) ^ ((r) >> 1)) & 3) << 4))
#define GTILE 8192
#define GSTG  (3 * GTILE)          // 24576
#define GEMM_SMEM (3 * GSTG)       // 73728 -> 2 CTAs/SM

__device__ __forceinline__ void gemm_mainloop(
    const __half* __restrict__ Ah, const __half* __restrict__ Al,
    const __half* __restrict__ Bh,
    int Kd, int bm, int bnB, float acc[4][8][4], char* smem)
{
    const uint32_t sbase = smem_u32(smem);
    const int tid  = threadIdx.x;
    const int wid  = tid >> 5;          // 0..3
    const int lane = tid & 31;
    const int nch  = Kd >> 5;

    const int mw = (wid >> 1) * 64;
    const int nw = (wid & 1) * 64;

    const int rowA = mw + (lane & 15);
    const int uA   = (lane >> 4) & 1;
    const int rowB = nw + (lane & 7) + ((lane >> 4) << 3);
    const int uB   = (lane >> 3) & 1;

#pragma unroll
    for (int mt = 0; mt < 4; ++mt)
#pragma unroll
        for (int nb = 0; nb < 8; ++nb)
#pragma unroll
            for (int q = 0; q < 4; ++q) acc[mt][nb][q] = 0.f;

    // stage loader: 1536 x 16B segments, 12 per thread (128 threads)
    auto load_stage = [&](int ci, int slot) {
        const int k0 = ci << 5;
        const uint32_t st = sbase + slot * GSTG;
#pragma unroll
        for (int it = 0; it < 12; ++it) {
            int u = tid + it * 128;
            int mat = u >> 9;            // 0 Ah, 1 Al, 2 B
            int v = u & 511;
            int row = v >> 2;
            int seg = v & 3;
            const __half* src;
            if (mat == 0)      src = Ah + (size_t)(bm + row) * Kd + k0 + seg * 8;
            else if (mat == 1) src = Al + (size_t)(bm + row) * Kd + k0 + seg * 8;
            else               src = Bh + (size_t)(bnB + row) * Kd + k0 + seg * 8;
            cp_async16(st + mat * GTILE + GSWZ(row, seg), src);
        }
        CP_COMMIT();
    };

    load_stage(0, 0);
    load_stage(1, 1);

    int slot = 0;
    for (int i = 0; i < nch; ++i) {
        if (i + 1 < nch) { CP_WAIT(1); } else { CP_WAIT(0); }
        __syncthreads();
        if (i + 2 < nch) load_stage(i + 2, (slot + 2) % 3);

        const uint32_t sb = sbase + slot * GSTG;
#pragma unroll
        for (int kk2 = 0; kk2 < 2; ++kk2) {
            uint32_t fAh[4][4], fAl[4][4];
#pragma unroll
            for (int mt = 0; mt < 4; ++mt) {
                uint32_t sw = GSWZ(rowA + mt * 16, kk2 * 2 + uA);
                ldm4(fAh[mt], sb + sw);
                ldm4(fAl[mt], sb + GTILE + sw);
            }
#pragma unroll
            for (int np = 0; np < 4; ++np) {
                uint32_t fB[4];
                uint32_t sw = GSWZ(np * 16 + rowB, kk2 * 2 + uB);
                ldm4(fB, sb + 2 * GTILE + sw);
#pragma unroll
                for (int half = 0; half < 2; ++half) {
                    int nb = np * 2 + half;
#pragma unroll
                    for (int mt = 0; mt < 4; ++mt)
                        mma16816h(acc[mt][nb], fAh[mt], &fB[half * 2]);
#pragma unroll
                    for (int mt = 0; mt < 4; ++mt)
                        mma16816h(acc[mt][nb], fAl[mt], &fB[half * 2]);
                }
            }
        }
        slot = (slot + 1) % 3;
    }
    __syncthreads();
}

// ---- QKV GEMM with fused RoPE (table) + bf16 hi/lo split epilogue ----------
__global__ __launch_bounds__(128) void qkv_gemm_kernel()
{
    extern __shared__ char smem[];
    const int bn = blockIdx.x * 128;
    const int bm = blockIdx.y * 128;

    float acc[4][8][4];
    gemm_mainloop(g_Xhi, g_Xlo, g_Wt_h, HID, bm, bn, acc, smem);

    const int tid  = threadIdx.x;
    const int wid  = tid >> 5;
    const int lane = tid & 31;
    const int mw = (wid >> 1) * 64;
    const int nw = (wid & 1) * 64;

    float* sm = (float*)smem;
#pragma unroll
    for (int mt = 0; mt < 4; ++mt)
#pragma unroll
        for (int nb = 0; nb < 8; ++nb) {
            int r0 = mw + mt * 16 + (lane >> 2);
            int c0 = nw + nb * 8 + (lane & 3) * 2;
            *(float2*)&sm[r0 * 132 + c0]       = make_float2(acc[mt][nb][0], acc[mt][nb][1]);
            *(float2*)&sm[(r0 + 8) * 132 + c0] = make_float2(acc[mt][nb][2], acc[mt][nb][3]);
        }
    __syncthreads();

    const bool isV = (bn >= HID + 512);
    __nv_bfloat16 *Dh, *Dl;
    int ldd, cbase;
    if (bn < HID)            { Dh = g_Qh; Dl = g_Ql; ldd = HID;    cbase = bn; }
    else if (bn < HID + 512) { Dh = g_Kh; Dl = g_Kl; ldd = KV_DIM; cbase = bn - HID; }
    else                     { Dh = g_Vh; Dl = g_Vl; ldd = KV_DIM; cbase = bn - HID - 512; }

#pragma unroll
    for (int k = 0; k < 16; ++k) {
        int u = tid + k * 128;
        int row = u >> 4;
        int i0 = (u & 15) * 4;
        float y0[4], y1[4];
        if (!isV) {
            float4 cv = *(const float4*)&g_rope_cos[(size_t)(bm + row) * 64 + i0];
            float4 sv = *(const float4*)&g_rope_sin[(size_t)(bm + row) * 64 + i0];
            float c[4] = {cv.x, cv.y, cv.z, cv.w};
            float s[4] = {sv.x, sv.y, sv.z, sv.w};
#pragma unroll
            for (int j = 0; j < 4; ++j) {
                float x0 = sm[row * 132 + i0 + j];
                float x1 = sm[row * 132 + i0 + j + 64];
                y0[j] = x0 * c[j] - x1 * s[j];
                y1[j] = x1 * c[j] + x0 * s[j];
            }
        } else {
#pragma unroll
            for (int j = 0; j < 4; ++j) {
                y0[j] = sm[row * 132 + i0 + j];
                y1[j] = sm[row * 132 + i0 + j + 64];
            }
        }
        size_t d0 = (size_t)(bm + row) * ldd + cbase + i0;
        size_t d1 = d0 + 64;
        __nv_bfloat16 h[8]; float r[8];
#pragma unroll
        for (int j = 0; j < 4; ++j) {
            h[j]     = __float2bfloat16(y0[j]);
            r[j]     = y0[j] - __bfloat162float(h[j]);
            h[j + 4] = __float2bfloat16(y1[j]);
            r[j + 4] = y1[j] - __bfloat162float(h[j + 4]);
        }
        *(__nv_bfloat162*)&Dh[d0]     = __halves2bfloat162(h[0], h[1]);
        *(__nv_bfloat162*)&Dh[d0 + 2] = __halves2bfloat162(h[2], h[3]);
        *(__nv_bfloat162*)&Dh[d1]     = __halves2bfloat162(h[4], h[5]);
        *(__nv_bfloat162*)&Dh[d1 + 2] = __halves2bfloat162(h[6], h[7]);
        *(__nv_bfloat162*)&Dl[d0]     = __floats2bfloat162_rn(r[0], r[1]);
        *(__nv_bfloat162*)&Dl[d0 + 2] = __floats2bfloat162_rn(r[2], r[3]);
        *(__nv_bfloat162*)&Dl[d1]     = __floats2bfloat162_rn(r[4], r[5]);
        *(__nv_bfloat162*)&Dl[d1 + 2] = __floats2bfloat162_rn(r[6], r[7]);
    }
}

// ---- output projection GEMM (direct fp32 store epilogue) --------------------
__global__ __launch_bounds__(128) void out_gemm_kernel(float* __restrict__ out)
{
    extern __shared__ char smem[];
    const int bn = blockIdx.x * 128;
    const int bm = blockIdx.y * 128;

    float acc[4][8][4];
    gemm_mainloop(g_Ahi, g_Alo, g_Wo_h, HID, bm, bn, acc, smem);

    const int tid  = threadIdx.x;
    const int wid  = tid >> 5;
    const int lane = tid & 31;
    const int mw = (wid >> 1) * 64;
    const int nw = (wid & 1) * 64;

#pragma unroll
    for (int mt = 0; mt < 4; ++mt)
#pragma unroll
        for (int nb = 0; nb < 8; ++nb) {
            int r0 = bm + mw + mt * 16 + (lane >> 2);
            int c0 = bn + nw + nb * 8 + (lane & 3) * 2;
            float2 v0 = {acc[mt][nb][0], acc[mt][nb][1]};
            float2 v1 = {acc[mt][nb][2], acc[mt][nb][3]};
            *(float2*)(out + (size_t)r0 * HID + c0)       = v0;
            *(float2*)(out + (size_t)(r0 + 8) * HID + c0) = v1;
        }
}

// ---------------- HMMA bf16x3 flash attention (swizzled, 96 KB smem) ---------
#define FSWZ(r, cb) ((((r) << 8) + (cb)) ^ (((r) & 7) << 4))
#define F_QH 0
#define F_QL 16384
#define F_KH 32768
#define F_KL 49152
#define F_VH 65536
#define F_VL 81920
#define FLASH_SMEM 98304

__global__ __launch_bounds__(128) void flash_kernel()
{
    const int qt  = (int)gridDim.x - 1 - (int)blockIdx.x;
    const int h   = blockIdx.y;
    const int kvh = h / (NH / NKV);

    extern __shared__ char fsm[];
    const uint32_t sb = smem_u32(fsm);

    const int tid  = threadIdx.x;
    const int w    = tid >> 5;
    const int lane = tid & 31;

    const int rowA   = w * 16 + (lane & 15);
    const int colA   = (lane >> 4) << 3;
    const int rowBo  = (lane & 7) + ((lane >> 4) << 3);
    const int colB   = ((lane >> 3) & 1) << 3;
    const int rowVt  = (lane & 7) + (((lane >> 3) & 1) << 3);
    const int colVt  = (lane >> 4) << 3;

    for (int f = tid; f < 1024; f += 128) {
        int r = f >> 4, cb = (f & 15) * 16;
        size_t g = (size_t)(qt * 64 + r) * HID + h * 128 + (f & 15) * 8;
        *(uint4*)(fsm + F_QH + FSWZ(r, cb)) = *(const uint4*)&g_Qh[g];
        *(uint4*)(fsm + F_QL + FSWZ(r, cb)) = *(const uint4*)&g_Ql[g];
    }

    float o[16][4];
#pragma unroll
    for (int nb = 0; nb < 16; ++nb)
#pragma unroll
        for (int q = 0; q < 4; ++q) o[nb][q] = 0.f;
    float m0 = -1e30f, m1 = -1e30f, l0 = 0.f, l1 = 0.f;

    const float SL = 0.08838834764831845f * 1.4426950408889634f;

    for (int kt = 0; kt <= qt; ++kt) {
        __syncthreads();
        for (int f = tid; f < 1024; f += 128) {
            int r = f >> 4, cb = (f & 15) * 16;
            size_t g = (size_t)(kt * 64 + r) * KV_DIM + kvh * 128 + (f & 15) * 8;
            uint32_t sw = FSWZ(r, cb);
            *(uint4*)(fsm + F_KH + sw) = *(const uint4*)&g_Kh[g];
            *(uint4*)(fsm + F_KL + sw) = *(const uint4*)&g_Kl[g];
            *(uint4*)(fsm + F_VH + sw) = *(const uint4*)&g_Vh[g];
            *(uint4*)(fsm + F_VL + sw) = *(const uint4*)&g_Vl[g];
        }
        __syncthreads();

        float s[8][4];
#pragma unroll
        for (int nb = 0; nb < 8; ++nb)
#pragma unroll
            for (int q = 0; q < 4; ++q) s[nb][q] = 0.f;

#pragma unroll
        for (int ks = 0; ks < 8; ++ks) {
            uint32_t qh[4], ql[4];
            uint32_t swa = FSWZ(rowA, ks * 32 + colA * 2);
            ldm4(qh, sb + F_QH + swa);
            ldm4(ql, sb + F_QL + swa);
#pragma unroll
            for (int np = 0; np < 4; ++np) {
                uint32_t kh[4], kl[4];
                uint32_t swb = FSWZ(np * 16 + rowBo, ks * 32 + colB * 2);
                ldm4(kh, sb + F_KH + swb);
                ldm4(kl, sb + F_KL + swb);
#pragma unroll
                for (int half = 0; half < 2; ++half) {
                    int nb = np * 2 + half;
                    mma16816(s[nb], qh, &kh[half * 2]);
                    mma16816(s[nb], qh, &kl[half * 2]);
                    mma16816(s[nb], ql, &kh[half * 2]);
                }
            }
        }

        const bool diag = (kt == qt);
        const int rl0 = w * 16 + (lane >> 2);
        const int rl1 = rl0 + 8;
        float mx0 = -1e30f, mx1 = -1e30f;
#pragma unroll
        for (int nb = 0; nb < 8; ++nb) {
            int c0 = nb * 8 + (lane & 3) * 2;
#pragma unroll
            for (int q = 0; q < 4; ++q) {
                float v = s[nb][q] * SL;
                if (diag) {
                    int col = c0 + (q & 1);
                    int row = (q < 2) ? rl0 : rl1;
                    if (col > row) v = -1e30f;
                }
                s[nb][q] = v;
            }
            mx0 = fmaxf(mx0, fmaxf(s[nb][0], s[nb][1]));
            mx1 = fmaxf(mx1, fmaxf(s[nb][2], s[nb][3]));
        }
        mx0 = fmaxf(mx0, __shfl_xor_sync(0xffffffffu, mx0, 1));
        mx0 = fmaxf(mx0, __shfl_xor_sync(0xffffffffu, mx0, 2));
        mx1 = fmaxf(mx1, __shfl_xor_sync(0xffffffffu, mx1, 1));
        mx1 = fmaxf(mx1, __shfl_xor_sync(0xffffffffu, mx1, 2));

        float mn0 = fmaxf(m0, mx0), mn1 = fmaxf(m1, mx1);
        float a0 = exp2f(m0 - mn0), a1 = exp2f(m1 - mn1);
        float ls0 = 0.f, ls1 = 0.f;
#pragma unroll
        for (int nb = 0; nb < 8; ++nb) {
            float p0 = exp2f(s[nb][0] - mn0);
            float p1 = exp2f(s[nb][1] - mn0);
            float p2 = exp2f(s[nb][2] - mn1);
            float p3 = exp2f(s[nb][3] - mn1);
            s[nb][0] = p0; s[nb][1] = p1; s[nb][2] = p2; s[nb][3] = p3;
            ls0 += p0 + p1;
            ls1 += p2 + p3;
        }
        ls0 += __shfl_xor_sync(0xffffffffu, ls0, 1);
        ls0 += __shfl_xor_sync(0xffffffffu, ls0, 2);
        ls1 += __shfl_xor_sync(0xffffffffu, ls1, 1);
        ls1 += __shfl_xor_sync(0xffffffffu, ls1, 2);
        l0 = l0 * a0 + ls0;
        l1 = l1 * a1 + ls1;
        m0 = mn0; m1 = mn1;

#pragma unroll
        for (int nb = 0; nb < 16; ++nb) {
            o[nb][0] *= a0; o[nb][1] *= a0;
            o[nb][2] *= a1; o[nb][3] *= a1;
        }

        uint32_t pah[4][4], pal[4][4];
#pragma unroll
        for (int kb = 0; kb < 4; ++kb) {
#pragma unroll
            for (int part = 0; part < 4; ++part) {
                int nb = 2 * kb + (part >> 1);
                float c0 = s[nb][(part & 1) * 2];
                float c1 = s[nb][(part & 1) * 2 + 1];
                __nv_bfloat162 hi2 = __floats2bfloat162_rn(c0, c1);
                pah[kb][part] = *(uint32_t*)&hi2;
                float r0 = c0 - __bfloat162float(hi2.x);
                float r1 = c1 - __bfloat162float(hi2.y);
                pal[kb][part] = packbf2(r0, r1);
            }
        }

#pragma unroll
        for (int kb = 0; kb < 4; ++kb) {
#pragma unroll
            for (int nv = 0; nv < 8; ++nv) {
                uint32_t vh[4], vl[4];
                uint32_t swv = FSWZ(kb * 16 + rowVt, nv * 32 + colVt * 2);
                ldm4t(vh, sb + F_VH + swv);
                ldm4t(vl, sb + F_VL + swv);
#pragma unroll
                for (int half = 0; half < 2; ++half) {
                    int nbv = nv * 2 + half;
                    mma16816(o[nbv], pah[kb], &vh[half * 2]);
                    mma16816(o[nbv], pal[kb], &vh[half * 2]);
                    mma16816(o[nbv], pah[kb], &vl[half * 2]);
                }
            }
        }
    }

    // normalize + write fp16 hi/lo for the fp16x2 out-projection
    const float inv0 = 1.0f / l0, inv1 = 1.0f / l1;
    const int r0 = qt * 64 + w * 16 + (lane >> 2);
    const int r1 = r0 + 8;
#pragma unroll
    for (int nb = 0; nb < 16; ++nb) {
        int c = h * 128 + nb * 8 + (lane & 3) * 2;
        float y0 = o[nb][0] * inv0, y1 = o[nb][1] * inv0;
        float y2 = o[nb][2] * inv1, y3 = o[nb][3] * inv1;
        __half2 h01 = __floats2half2_rn(y0, y1);
        __half2 h23 = __floats2half2_rn(y2, y3);
        *(__half2*)&g_Ahi[(size_t)r0 * HID + c] = h01;
        *(__half2*)&g_Ahi[(size_t)r1 * HID + c] = h23;
        __half2 l01 = __floats2half2_rn(y0 - __half2float(__low2half(h01)),
                                        y1 - __half2float(__high2half(h01)));
        __half2 l23 = __floats2half2_rn(y2 - __half2float(__low2half(h23)),
                                        y3 - __half2float(__high2half(h23)));
        *(__half2*)&g_Alo[(size_t)r0 * HID + c] = l01;
        *(__half2*)&g_Alo[(size_t)r1 * HID + c] = l23;
    }
}

// ---------------------------------------------------------------------------
extern "C" void kernel_launch(void* const* d_in, const int* in_sizes, int n_in,
                              void* d_out, int out_size)
{
    const float* X   = (const float*)d_in[0];
    const int*   pid = (const int*)  d_in[1];
    const float* Wq  = (const float*)d_in[2];
    const float* Wk  = (const float*)d_in[3];
    const float* Wv  = (const float*)d_in[4];
    const float* Wo  = (const float*)d_in[5];
    float* out = (float*)d_out;

    static int attr_set = 0;
    if (!attr_set) {
        cudaFuncSetAttribute(qkv_gemm_kernel, cudaFuncAttributeMaxDynamicSharedMemorySize, GEMM_SMEM);
        cudaFuncSetAttribute(out_gemm_kernel, cudaFuncAttributeMaxDynamicSharedMemorySize, GEMM_SMEM);
        cudaFuncSetAttribute(flash_kernel, cudaFuncAttributeMaxDynamicSharedMemorySize, FLASH_SMEM);
        attr_set = 1;
    }

    split_x_kernel<<<(S_LEN * HID + 255) / 256, 256>>>(X);
    transpose_h<<<dim3(HID / 32, HID / 32), dim3(32, 8)>>>(Wq, HID, HID, 0, 0);
    transpose_h<<<dim3(KV_DIM / 32, HID / 32), dim3(32, 8)>>>(
        Wk, HID, KV_DIM, 0, (size_t)HID * HID);
    transpose_h<<<dim3(KV_DIM / 32, HID / 32), dim3(32, 8)>>>(
        Wv, HID, KV_DIM, 0, (size_t)(HID + 512) * HID);
    rope_table_kernel<<<(S_LEN * 64 + 255) / 256, 256>>>(pid);

    qkv_gemm_kernel<<<dim3(QKV_N / 128, S_LEN / 128), 128, GEMM_SMEM>>>();

    transpose_h<<<dim3(HID / 32, HID / 32), dim3(32, 8)>>>(Wo, HID, HID, 1, 0);

    flash_kernel<<<dim3(32, 28), 128, FLASH_SMEM>>>();

    out_gemm_kernel<<<dim3(HID / 128, S_LEN / 128), 128, GEMM_SMEM>>>(out);
}

// round 16
// speedup vs baseline: 1.4846x; 1.0671x over previous
#include <cuda_runtime.h>
#include <cuda_bf16.h>
#include <cuda_fp16.h>
#include <math.h>
#include <stdint.h>

#define S_LEN 2048
#define HID   3584
#define NH    28
#define NKV   4
#define HD    128
#define KV_DIM 512
#define QKV_N  4608   // 3584 + 512 + 512

// ---------------- scratch (__device__ globals; no allocs allowed) ----------
__device__ __half g_Xhi[S_LEN * HID];
__device__ __half g_Xlo[S_LEN * HID];
__device__ __half g_Ahi[S_LEN * HID];
__device__ __half g_Alo[S_LEN * HID];
__device__ __half g_Wt_h[(size_t)QKV_N * HID];
__device__ __half g_Wo_h[(size_t)HID * HID];

__device__ __nv_bfloat16 g_Qh[S_LEN * HID];
__device__ __nv_bfloat16 g_Ql[S_LEN * HID];
__device__ __nv_bfloat16 g_Kh[S_LEN * KV_DIM];
__device__ __nv_bfloat16 g_Kl[S_LEN * KV_DIM];
__device__ __nv_bfloat16 g_Vh[S_LEN * KV_DIM];
__device__ __nv_bfloat16 g_Vl[S_LEN * KV_DIM];

__device__ float g_rope_cos[S_LEN * 64];
__device__ float g_rope_sin[S_LEN * 64];

// ---------------- PTX helpers (baseline PTX only) ---------------------------
__device__ __forceinline__ uint32_t smem_u32(const void* p) {
    uint32_t a;
    asm("{ .reg .u64 t; cvta.to.shared.u64 t, %1; cvt.u32.u64 %0, t; }" : "=r"(a) : "l"(p));
    return a;
}
__device__ __forceinline__ void cp_async16(uint32_t dst, const void* src) {
    asm volatile("cp.async.cg.shared.global [%0], [%1], 16;" :: "r"(dst), "l"(src));
}
#define CP_COMMIT() asm volatile("cp.async.commit_group;" ::: "memory")
#define CP_WAIT(N)  asm volatile("cp.async.wait_group %0;" :: "n"(N) : "memory")

__device__ __forceinline__ void ldm4(uint32_t* r, uint32_t addr) {
    asm volatile("ldmatrix.sync.aligned.m8n8.x4.shared.b16 {%0,%1,%2,%3}, [%4];"
        : "=r"(r[0]), "=r"(r[1]), "=r"(r[2]), "=r"(r[3]) : "r"(addr));
}
__device__ __forceinline__ void ldm4t(uint32_t* r, uint32_t addr) {
    asm volatile("ldmatrix.sync.aligned.m8n8.x4.trans.shared.b16 {%0,%1,%2,%3}, [%4];"
        : "=r"(r[0]), "=r"(r[1]), "=r"(r[2]), "=r"(r[3]) : "r"(addr));
}
__device__ __forceinline__ void mma16816(float* c, const uint32_t* a, const uint32_t* b) {
    asm volatile("mma.sync.aligned.m16n8k16.row.col.f32.bf16.bf16.f32 "
        "{%0,%1,%2,%3}, {%4,%5,%6,%7}, {%8,%9}, {%0,%1,%2,%3};"
        : "+f"(c[0]), "+f"(c[1]), "+f"(c[2]), "+f"(c[3])
        : "r"(a[0]), "r"(a[1]), "r"(a[2]), "r"(a[3]), "r"(b[0]), "r"(b[1]));
}
__device__ __forceinline__ void mma16816h(float* c, const uint32_t* a, const uint32_t* b) {
    asm volatile("mma.sync.aligned.m16n8k16.row.col.f32.f16.f16.f32 "
        "{%0,%1,%2,%3}, {%4,%5,%6,%7}, {%8,%9}, {%0,%1,%2,%3};"
        : "+f"(c[0]), "+f"(c[1]), "+f"(c[2]), "+f"(c[3])
        : "r"(a[0]), "r"(a[1]), "r"(a[2]), "r"(a[3]), "r"(b[0]), "r"(b[1]));
}
__device__ __forceinline__ uint32_t packbf2(float lo, float hi) {
    __nv_bfloat162 t = __floats2bfloat162_rn(lo, hi);
    return *(uint32_t*)&t;
}

// ---------------- pre-processing kernels ------------------------------------
__global__ void split_x_kernel(const float* __restrict__ X) {
    int i = blockIdx.x * blockDim.x + threadIdx.x;
    if (i < S_LEN * HID) {
        float x = X[i];
        __half h = __float2half_rn(x);
        g_Xhi[i] = h;
        g_Xlo[i] = __float2half_rn(x - __half2float(h));
    }
}

__global__ void rope_table_kernel(const int* __restrict__ pid) {
    int idx = blockIdx.x * blockDim.x + threadIdx.x;
    if (idx < S_LEN * 64) {
        int s = idx >> 6, i = idx & 63;
        float inv_freq = expf(-(float)i * 0.21586735246819178f);
        float sv, cv;
        sincosf((float)pid[s] * inv_freq, &sv, &cv);
        g_rope_cos[idx] = cv;
        g_rope_sin[idx] = sv;
    }
}

// all four weight transposes in one launch (blockIdx.z selects the matrix)
__global__ void transpose_all(const float* __restrict__ Wq,
                              const float* __restrict__ Wk,
                              const float* __restrict__ Wv,
                              const float* __restrict__ Wo) {
    const float* W;
    __half* Th;
    int N;
    switch (blockIdx.z) {
        case 0: W = Wq; Th = g_Wt_h;                               N = HID;    break;
        case 1: W = Wk; Th = g_Wt_h + (size_t)HID * HID;           N = KV_DIM; break;
        case 2: W = Wv; Th = g_Wt_h + (size_t)(HID + 512) * HID;   N = KV_DIM; break;
        default: W = Wo; Th = g_Wo_h;                              N = HID;    break;
    }
    int n0 = blockIdx.x * 32, k0 = blockIdx.y * 32;
    if (n0 >= N) return;
    __shared__ float t[32][33];
    int tx = threadIdx.x, ty = threadIdx.y;
#pragma unroll
    for (int i = 0; i < 32; i += 8)
        t[ty + i][tx] = W[(size_t)(k0 + ty + i) * N + n0 + tx];
    __syncthreads();
#pragma unroll
    for (int i = 0; i < 32; i += 8) {
        int n = n0 + ty + i, k = k0 + tx;
        Th[(size_t)n * HID + k] = __float2half_rn(t[tx][ty + i]);
    }
}

// ---------------- fp16x2 HMMA GEMM: BK=64, 2-stage, single barrier ----------
// Tile: 128 rows x 64 fp16 = 128 B/row = 8 x 16B units; swizzle u' = u ^ (r&7)
#define GSWZ(r, u) (((r) << 7) + ((((u) ^ (r)) & 7) << 4))
#define GTILE 16384
#define GSTG  (3 * GTILE)          // Ah | Al | B = 49152
#define GEMM_SMEM (2 * GSTG)       // 98304 -> 2 CTAs/SM

__device__ __forceinline__ void gemm_mainloop(
    const __half* __restrict__ Ah, const __half* __restrict__ Al,
    const __half* __restrict__ Bh,
    int Kd, int bm, int bnB, float acc[4][8][4], char* smem)
{
    const uint32_t sbase = smem_u32(smem);
    const int tid  = threadIdx.x;
    const int wid  = tid >> 5;
    const int lane = tid & 31;
    const int nch  = Kd >> 6;           // BK = 64

    const int mw = (wid >> 1) * 64;
    const int nw = (wid & 1) * 64;

    const int rowA = mw + (lane & 15);
    const int uA   = (lane >> 4) & 1;
    const int rowB = nw + (lane & 7) + ((lane >> 4) << 3);
    const int uB   = (lane >> 3) & 1;

#pragma unroll
    for (int mt = 0; mt < 4; ++mt)
#pragma unroll
        for (int nb = 0; nb < 8; ++nb)
#pragma unroll
            for (int q = 0; q < 4; ++q) acc[mt][nb][q] = 0.f;

    // stage loader: 3072 x 16B segments, 24 per thread (128 threads)
    auto load_stage = [&](int ci, int slot) {
        const int k0 = ci << 6;
        const uint32_t st = sbase + slot * GSTG;
#pragma unroll
        for (int it = 0; it < 24; ++it) {
            int u = tid + it * 128;
            int mat = u >> 10;           // 0 Ah, 1 Al, 2 B
            int v = u & 1023;
            int row = v >> 3;
            int seg = v & 7;
            const __half* src;
            if (mat == 0)      src = Ah + (size_t)(bm + row) * Kd + k0 + seg * 8;
            else if (mat == 1) src = Al + (size_t)(bm + row) * Kd + k0 + seg * 8;
            else               src = Bh + (size_t)(bnB + row) * Kd + k0 + seg * 8;
            cp_async16(st + mat * GTILE + GSWZ(row, seg), src);
        }
        CP_COMMIT();
    };

    load_stage(0, 0);

    for (int i = 0; i < nch; ++i) {
        CP_WAIT(0);                  // stage i fully resident
        __syncthreads();             // all warps done computing stage i-1
        if (i + 1 < nch) load_stage(i + 1, (i + 1) & 1);  // overlaps compute(i)

        const uint32_t sb = sbase + (i & 1) * GSTG;
#pragma unroll
        for (int kk2 = 0; kk2 < 4; ++kk2) {     // kk = kk2*16 within BK=64
            uint32_t fAh[4][4], fAl[4][4];
#pragma unroll
            for (int mt = 0; mt < 4; ++mt) {
                uint32_t sw = GSWZ(rowA + mt * 16, kk2 * 2 + uA);
                ldm4(fAh[mt], sb + sw);
                ldm4(fAl[mt], sb + GTILE + sw);
            }
#pragma unroll
            for (int np = 0; np < 4; ++np) {
                uint32_t fB[4];
                uint32_t sw = GSWZ(np * 16 + rowB, kk2 * 2 + uB);
                ldm4(fB, sb + 2 * GTILE + sw);
#pragma unroll
                for (int half = 0; half < 2; ++half) {
                    int nb = np * 2 + half;
#pragma unroll
                    for (int mt = 0; mt < 4; ++mt)
                        mma16816h(acc[mt][nb], fAh[mt], &fB[half * 2]);
#pragma unroll
                    for (int mt = 0; mt < 4; ++mt)
                        mma16816h(acc[mt][nb], fAl[mt], &fB[half * 2]);
                }
            }
        }
    }
    __syncthreads();   // all warps done before epilogue smem reuse
}

// ---- QKV GEMM with fused RoPE (table) + bf16 hi/lo split epilogue ----------
__global__ __launch_bounds__(128) void qkv_gemm_kernel()
{
    extern __shared__ char smem[];
    const int bn = blockIdx.x * 128;
    const int bm = blockIdx.y * 128;

    float acc[4][8][4];
    gemm_mainloop(g_Xhi, g_Xlo, g_Wt_h, HID, bm, bn, acc, smem);

    const int tid  = threadIdx.x;
    const int wid  = tid >> 5;
    const int lane = tid & 31;
    const int mw = (wid >> 1) * 64;
    const int nw = (wid & 1) * 64;

    float* sm = (float*)smem;
#pragma unroll
    for (int mt = 0; mt < 4; ++mt)
#pragma unroll
        for (int nb = 0; nb < 8; ++nb) {
            int r0 = mw + mt * 16 + (lane >> 2);
            int c0 = nw + nb * 8 + (lane & 3) * 2;
            *(float2*)&sm[r0 * 132 + c0]       = make_float2(acc[mt][nb][0], acc[mt][nb][1]);
            *(float2*)&sm[(r0 + 8) * 132 + c0] = make_float2(acc[mt][nb][2], acc[mt][nb][3]);
        }
    __syncthreads();

    const bool isV = (bn >= HID + 512);
    __nv_bfloat16 *Dh, *Dl;
    int ldd, cbase;
    if (bn < HID)            { Dh = g_Qh; Dl = g_Ql; ldd = HID;    cbase = bn; }
    else if (bn < HID + 512) { Dh = g_Kh; Dl = g_Kl; ldd = KV_DIM; cbase = bn - HID; }
    else                     { Dh = g_Vh; Dl = g_Vl; ldd = KV_DIM; cbase = bn - HID - 512; }

#pragma unroll
    for (int k = 0; k < 16; ++k) {
        int u = tid + k * 128;
        int row = u >> 4;
        int i0 = (u & 15) * 4;
        float y0[4], y1[4];
        if (!isV) {
            float4 cv = *(const float4*)&g_rope_cos[(size_t)(bm + row) * 64 + i0];
            float4 sv = *(const float4*)&g_rope_sin[(size_t)(bm + row) * 64 + i0];
            float c[4] = {cv.x, cv.y, cv.z, cv.w};
            float s[4] = {sv.x, sv.y, sv.z, sv.w};
#pragma unroll
            for (int j = 0; j < 4; ++j) {
                float x0 = sm[row * 132 + i0 + j];
                float x1 = sm[row * 132 + i0 + j + 64];
                y0[j] = x0 * c[j] - x1 * s[j];
                y1[j] = x1 * c[j] + x0 * s[j];
            }
        } else {
#pragma unroll
            for (int j = 0; j < 4; ++j) {
                y0[j] = sm[row * 132 + i0 + j];
                y1[j] = sm[row * 132 + i0 + j + 64];
            }
        }
        size_t d0 = (size_t)(bm + row) * ldd + cbase + i0;
        size_t d1 = d0 + 64;
        __nv_bfloat16 h[8]; float r[8];
#pragma unroll
        for (int j = 0; j < 4; ++j) {
            h[j]     = __float2bfloat16(y0[j]);
            r[j]     = y0[j] - __bfloat162float(h[j]);
            h[j + 4] = __float2bfloat16(y1[j]);
            r[j + 4] = y1[j] - __bfloat162float(h[j + 4]);
        }
        *(__nv_bfloat162*)&Dh[d0]     = __halves2bfloat162(h[0], h[1]);
        *(__nv_bfloat162*)&Dh[d0 + 2] = __halves2bfloat162(h[2], h[3]);
        *(__nv_bfloat162*)&Dh[d1]     = __halves2bfloat162(h[4], h[5]);
        *(__nv_bfloat162*)&Dh[d1 + 2] = __halves2bfloat162(h[6], h[7]);
        *(__nv_bfloat162*)&Dl[d0]     = __floats2bfloat162_rn(r[0], r[1]);
        *(__nv_bfloat162*)&Dl[d0 + 2] = __floats2bfloat162_rn(r[2], r[3]);
        *(__nv_bfloat162*)&Dl[d1]     = __floats2bfloat162_rn(r[4], r[5]);
        *(__nv_bfloat162*)&Dl[d1 + 2] = __floats2bfloat162_rn(r[6], r[7]);
    }
}

// ---- output projection GEMM (direct fp32 store epilogue) --------------------
__global__ __launch_bounds__(128) void out_gemm_kernel(float* __restrict__ out)
{
    extern __shared__ char smem[];
    const int bn = blockIdx.x * 128;
    const int bm = blockIdx.y * 128;

    float acc[4][8][4];
    gemm_mainloop(g_Ahi, g_Alo, g_Wo_h, HID, bm, bn, acc, smem);

    const int tid  = threadIdx.x;
    const int wid  = tid >> 5;
    const int lane = tid & 31;
    const int mw = (wid >> 1) * 64;
    const int nw = (wid & 1) * 64;

#pragma unroll
    for (int mt = 0; mt < 4; ++mt)
#pragma unroll
        for (int nb = 0; nb < 8; ++nb) {
            int r0 = bm + mw + mt * 16 + (lane >> 2);
            int c0 = bn + nw + nb * 8 + (lane & 3) * 2;
            float2 v0 = {acc[mt][nb][0], acc[mt][nb][1]};
            float2 v1 = {acc[mt][nb][2], acc[mt][nb][3]};
            *(float2*)(out + (size_t)r0 * HID + c0)       = v0;
            *(float2*)(out + (size_t)(r0 + 8) * HID + c0) = v1;
        }
}

// ---------------- HMMA bf16x3 flash attention (swizzled, 96 KB smem) ---------
#define FSWZ(r, cb) ((((r) << 8) + (cb)) ^ (((r) & 7) << 4))
#define F_QH 0
#define F_QL 16384
#define F_KH 32768
#define F_KL 49152
#define F_VH 65536
#define F_VL 81920
#define FLASH_SMEM 98304

__global__ __launch_bounds__(128) void flash_kernel()
{
    const int qt  = (int)gridDim.x - 1 - (int)blockIdx.x;
    const int h   = blockIdx.y;
    const int kvh = h / (NH / NKV);

    extern __shared__ char fsm[];
    const uint32_t sb = smem_u32(fsm);

    const int tid  = threadIdx.x;
    const int w    = tid >> 5;
    const int lane = tid & 31;

    const int rowA   = w * 16 + (lane & 15);
    const int colA   = (lane >> 4) << 3;
    const int rowBo  = (lane & 7) + ((lane >> 4) << 3);
    const int colB   = ((lane >> 3) & 1) << 3;
    const int rowVt  = (lane & 7) + (((lane >> 3) & 1) << 3);
    const int colVt  = (lane >> 4) << 3;

    for (int f = tid; f < 1024; f += 128) {
        int r = f >> 4, cb = (f & 15) * 16;
        size_t g = (size_t)(qt * 64 + r) * HID + h * 128 + (f & 15) * 8;
        *(uint4*)(fsm + F_QH + FSWZ(r, cb)) = *(const uint4*)&g_Qh[g];
        *(uint4*)(fsm + F_QL + FSWZ(r, cb)) = *(const uint4*)&g_Ql[g];
    }

    float o[16][4];
#pragma unroll
    for (int nb = 0; nb < 16; ++nb)
#pragma unroll
        for (int q = 0; q < 4; ++q) o[nb][q] = 0.f;
    float m0 = -1e30f, m1 = -1e30f, l0 = 0.f, l1 = 0.f;

    const float SL = 0.08838834764831845f * 1.4426950408889634f;

    for (int kt = 0; kt <= qt; ++kt) {
        __syncthreads();
        for (int f = tid; f < 1024; f += 128) {
            int r = f >> 4, cb = (f & 15) * 16;
            size_t g = (size_t)(kt * 64 + r) * KV_DIM + kvh * 128 + (f & 15) * 8;
            uint32_t sw = FSWZ(r, cb);
            *(uint4*)(fsm + F_KH + sw) = *(const uint4*)&g_Kh[g];
            *(uint4*)(fsm + F_KL + sw) = *(const uint4*)&g_Kl[g];
            *(uint4*)(fsm + F_VH + sw) = *(const uint4*)&g_Vh[g];
            *(uint4*)(fsm + F_VL + sw) = *(const uint4*)&g_Vl[g];
        }
        __syncthreads();

        float s[8][4];
#pragma unroll
        for (int nb = 0; nb < 8; ++nb)
#pragma unroll
            for (int q = 0; q < 4; ++q) s[nb][q] = 0.f;

#pragma unroll
        for (int ks = 0; ks < 8; ++ks) {
            uint32_t qh[4], ql[4];
            uint32_t swa = FSWZ(rowA, ks * 32 + colA * 2);
            ldm4(qh, sb + F_QH + swa);
            ldm4(ql, sb + F_QL + swa);
#pragma unroll
            for (int np = 0; np < 4; ++np) {
                uint32_t kh[4], kl[4];
                uint32_t swb = FSWZ(np * 16 + rowBo, ks * 32 + colB * 2);
                ldm4(kh, sb + F_KH + swb);
                ldm4(kl, sb + F_KL + swb);
#pragma unroll
                for (int half = 0; half < 2; ++half) {
                    int nb = np * 2 + half;
                    mma16816(s[nb], qh, &kh[half * 2]);
                    mma16816(s[nb], qh, &kl[half * 2]);
                    mma16816(s[nb], ql, &kh[half * 2]);
                }
            }
        }

        const bool diag = (kt == qt);
        const int rl0 = w * 16 + (lane >> 2);
        const int rl1 = rl0 + 8;
        float mx0 = -1e30f, mx1 = -1e30f;
#pragma unroll
        for (int nb = 0; nb < 8; ++nb) {
            int c0 = nb * 8 + (lane & 3) * 2;
#pragma unroll
            for (int q = 0; q < 4; ++q) {
                float v = s[nb][q] * SL;
                if (diag) {
                    int col = c0 + (q & 1);
                    int row = (q < 2) ? rl0 : rl1;
                    if (col > row) v = -1e30f;
                }
                s[nb][q] = v;
            }
            mx0 = fmaxf(mx0, fmaxf(s[nb][0], s[nb][1]));
            mx1 = fmaxf(mx1, fmaxf(s[nb][2], s[nb][3]));
        }
        mx0 = fmaxf(mx0, __shfl_xor_sync(0xffffffffu, mx0, 1));
        mx0 = fmaxf(mx0, __shfl_xor_sync(0xffffffffu, mx0, 2));
        mx1 = fmaxf(mx1, __shfl_xor_sync(0xffffffffu, mx1, 1));
        mx1 = fmaxf(mx1, __shfl_xor_sync(0xffffffffu, mx1, 2));

        float mn0 = fmaxf(m0, mx0), mn1 = fmaxf(m1, mx1);
        float a0 = exp2f(m0 - mn0), a1 = exp2f(m1 - mn1);
        float ls0 = 0.f, ls1 = 0.f;
#pragma unroll
        for (int nb = 0; nb < 8; ++nb) {
            float p0 = exp2f(s[nb][0] - mn0);
            float p1 = exp2f(s[nb][1] - mn0);
            float p2 = exp2f(s[nb][2] - mn1);
            float p3 = exp2f(s[nb][3] - mn1);
            s[nb][0] = p0; s[nb][1] = p1; s[nb][2] = p2; s[nb][3] = p3;
            ls0 += p0 + p1;
            ls1 += p2 + p3;
        }
        ls0 += __shfl_xor_sync(0xffffffffu, ls0, 1);
        ls0 += __shfl_xor_sync(0xffffffffu, ls0, 2);
        ls1 += __shfl_xor_sync(0xffffffffu, ls1, 1);
        ls1 += __shfl_xor_sync(0xffffffffu, ls1, 2);
        l0 = l0 * a0 + ls0;
        l1 = l1 * a1 + ls1;
        m0 = mn0; m1 = mn1;

#pragma unroll
        for (int nb = 0; nb < 16; ++nb) {
            o[nb][0] *= a0; o[nb][1] *= a0;
            o[nb][2] *= a1; o[nb][3] *= a1;
        }

        uint32_t pah[4][4], pal[4][4];
#pragma unroll
        for (int kb = 0; kb < 4; ++kb) {
#pragma unroll
            for (int part = 0; part < 4; ++part) {
                int nb = 2 * kb + (part >> 1);
                float c0 = s[nb][(part & 1) * 2];
                float c1 = s[nb][(part & 1) * 2 + 1];
                __nv_bfloat162 hi2 = __floats2bfloat162_rn(c0, c1);
                pah[kb][part] = *(uint32_t*)&hi2;
                float r0 = c0 - __bfloat162float(hi2.x);
                float r1 = c1 - __bfloat162float(hi2.y);
                pal[kb][part] = packbf2(r0, r1);
            }
        }

#pragma unroll
        for (int kb = 0; kb < 4; ++kb) {
#pragma unroll
            for (int nv = 0; nv < 8; ++nv) {
                uint32_t vh[4], vl[4];
                uint32_t swv = FSWZ(kb * 16 + rowVt, nv * 32 + colVt * 2);
                ldm4t(vh, sb + F_VH + swv);
                ldm4t(vl, sb + F_VL + swv);
#pragma unroll
                for (int half = 0; half < 2; ++half) {
                    int nbv = nv * 2 + half;
                    mma16816(o[nbv], pah[kb], &vh[half * 2]);
                    mma16816(o[nbv], pal[kb], &vh[half * 2]);
                    mma16816(o[nbv], pah[kb], &vl[half * 2]);
                }
            }
        }
    }

    // normalize + write fp16 hi/lo for the fp16x2 out-projection
    const float inv0 = 1.0f / l0, inv1 = 1.0f / l1;
    const int r0 = qt * 64 + w * 16 + (lane >> 2);
    const int r1 = r0 + 8;
#pragma unroll
    for (int nb = 0; nb < 16; ++nb) {
        int c = h * 128 + nb * 8 + (lane & 3) * 2;
        float y0 = o[nb][0] * inv0, y1 = o[nb][1] * inv0;
        float y2 = o[nb][2] * inv1, y3 = o[nb][3] * inv1;
        __half2 h01 = __floats2half2_rn(y0, y1);
        __half2 h23 = __floats2half2_rn(y2, y3);
        *(__half2*)&g_Ahi[(size_t)r0 * HID + c] = h01;
        *(__half2*)&g_Ahi[(size_t)r1 * HID + c] = h23;
        __half2 l01 = __floats2half2_rn(y0 - __half2float(__low2half(h01)),
                                        y1 - __half2float(__high2half(h01)));
        __half2 l23 = __floats2half2_rn(y2 - __half2float(__low2half(h23)),
                                        y3 - __half2float(__high2half(h23)));
        *(__half2*)&g_Alo[(size_t)r0 * HID + c] = l01;
        *(__half2*)&g_Alo[(size_t)r1 * HID + c] = l23;
    }
}

// ---------------------------------------------------------------------------
extern "C" void kernel_launch(void* const* d_in, const int* in_sizes, int n_in,
                              void* d_out, int out_size)
{
    const float* X   = (const float*)d_in[0];
    const int*   pid = (const int*)  d_in[1];
    const float* Wq  = (const float*)d_in[2];
    const float* Wk  = (const float*)d_in[3];
    const float* Wv  = (const float*)d_in[4];
    const float* Wo  = (const float*)d_in[5];
    float* out = (float*)d_out;

    static int attr_set = 0;
    if (!attr_set) {
        cudaFuncSetAttribute(qkv_gemm_kernel, cudaFuncAttributeMaxDynamicSharedMemorySize, GEMM_SMEM);
        cudaFuncSetAttribute(out_gemm_kernel, cudaFuncAttributeMaxDynamicSharedMemorySize, GEMM_SMEM);
        cudaFuncSetAttribute(flash_kernel, cudaFuncAttributeMaxDynamicSharedMemorySize, FLASH_SMEM);
        attr_set = 1;
    }

    split_x_kernel<<<(S_LEN * HID + 255) / 256, 256>>>(X);
    transpose_all<<<dim3(HID / 32, HID / 32, 4), dim3(32, 8)>>>(Wq, Wk, Wv, Wo);
    rope_table_kernel<<<(S_LEN * 64 + 255) / 256, 256>>>(pid);

    qkv_gemm_kernel<<<dim3(QKV_N / 128, S_LEN / 128), 128, GEMM_SMEM>>>();

    flash_kernel<<<dim3(32, 28), 128, FLASH_SMEM>>>();

    out_gemm_kernel<<<dim3(HID / 128, S_LEN / 128), 128, GEMM_SMEM>>>(out);
}

// round 17
// speedup vs baseline: 1.5221x; 1.0252x over previous
#include <cuda_runtime.h>
#include <cuda_bf16.h>
#include <cuda_fp16.h>
#include <math.h>
#include <stdint.h>

#define S_LEN 2048
#define HID   3584
#define NH    28
#define NKV   4
#define HD    128
#define KV_DIM 512
#define QKV_N  4608   // 3584 + 512 + 512

// ---------------- scratch (__device__ globals; no allocs allowed) ----------
__device__ __half g_Xhi[S_LEN * HID];
__device__ __half g_Xlo[S_LEN * HID];
__device__ __half g_Ahi[S_LEN * HID];
__device__ __half g_Alo[S_LEN * HID];
__device__ __half g_Wt_h[(size_t)QKV_N * HID];
__device__ __half g_Wo_h[(size_t)HID * HID];

__device__ __nv_bfloat16 g_Qh[S_LEN * HID];
__device__ __nv_bfloat16 g_Ql[S_LEN * HID];
__device__ __nv_bfloat16 g_Kh[S_LEN * KV_DIM];
__device__ __nv_bfloat16 g_Kl[S_LEN * KV_DIM];
__device__ __nv_bfloat16 g_Vh[S_LEN * KV_DIM];
__device__ __nv_bfloat16 g_Vl[S_LEN * KV_DIM];

__device__ float g_rope_cos[S_LEN * 64];
__device__ float g_rope_sin[S_LEN * 64];

// ---------------- PTX helpers (baseline PTX only) ---------------------------
__device__ __forceinline__ uint32_t smem_u32(const void* p) {
    uint32_t a;
    asm("{ .reg .u64 t; cvta.to.shared.u64 t, %1; cvt.u32.u64 %0, t; }" : "=r"(a) : "l"(p));
    return a;
}
__device__ __forceinline__ void cp_async16(uint32_t dst, const void* src) {
    asm volatile("cp.async.cg.shared.global [%0], [%1], 16;" :: "r"(dst), "l"(src));
}
#define CP_COMMIT() asm volatile("cp.async.commit_group;" ::: "memory")
#define CP_WAIT(N)  asm volatile("cp.async.wait_group %0;" :: "n"(N) : "memory")

__device__ __forceinline__ void ldm4(uint32_t* r, uint32_t addr) {
    asm volatile("ldmatrix.sync.aligned.m8n8.x4.shared.b16 {%0,%1,%2,%3}, [%4];"
        : "=r"(r[0]), "=r"(r[1]), "=r"(r[2]), "=r"(r[3]) : "r"(addr));
}
__device__ __forceinline__ void ldm4t(uint32_t* r, uint32_t addr) {
    asm volatile("ldmatrix.sync.aligned.m8n8.x4.trans.shared.b16 {%0,%1,%2,%3}, [%4];"
        : "=r"(r[0]), "=r"(r[1]), "=r"(r[2]), "=r"(r[3]) : "r"(addr));
}
__device__ __forceinline__ void mma16816(float* c, const uint32_t* a, const uint32_t* b) {
    asm volatile("mma.sync.aligned.m16n8k16.row.col.f32.bf16.bf16.f32 "
        "{%0,%1,%2,%3}, {%4,%5,%6,%7}, {%8,%9}, {%0,%1,%2,%3};"
        : "+f"(c[0]), "+f"(c[1]), "+f"(c[2]), "+f"(c[3])
        : "r"(a[0]), "r"(a[1]), "r"(a[2]), "r"(a[3]), "r"(b[0]), "r"(b[1]));
}
__device__ __forceinline__ void mma16816h(float* c, const uint32_t* a, const uint32_t* b) {
    asm volatile("mma.sync.aligned.m16n8k16.row.col.f32.f16.f16.f32 "
        "{%0,%1,%2,%3}, {%4,%5,%6,%7}, {%8,%9}, {%0,%1,%2,%3};"
        : "+f"(c[0]), "+f"(c[1]), "+f"(c[2]), "+f"(c[3])
        : "r"(a[0]), "r"(a[1]), "r"(a[2]), "r"(a[3]), "r"(b[0]), "r"(b[1]));
}
__device__ __forceinline__ uint32_t packbf2(float lo, float hi) {
    __nv_bfloat162 t = __floats2bfloat162_rn(lo, hi);
    return *(uint32_t*)&t;
}

// ---------------- pre-processing kernels ------------------------------------
__global__ void split_x_kernel(const float* __restrict__ X) {
    int i = blockIdx.x * blockDim.x + threadIdx.x;
    if (i < S_LEN * HID) {
        float x = X[i];
        __half h = __float2half_rn(x);
        g_Xhi[i] = h;
        g_Xlo[i] = __float2half_rn(x - __half2float(h));
    }
}

__global__ void rope_table_kernel(const int* __restrict__ pid) {
    int idx = blockIdx.x * blockDim.x + threadIdx.x;
    if (idx < S_LEN * 64) {
        int s = idx >> 6, i = idx & 63;
        float inv_freq = expf(-(float)i * 0.21586735246819178f);
        float sv, cv;
        sincosf((float)pid[s] * inv_freq, &sv, &cv);
        g_rope_cos[idx] = cv;
        g_rope_sin[idx] = sv;
    }
}

__global__ void transpose_all(const float* __restrict__ Wq,
                              const float* __restrict__ Wk,
                              const float* __restrict__ Wv,
                              const float* __restrict__ Wo) {
    const float* W;
    __half* Th;
    int N;
    switch (blockIdx.z) {
        case 0: W = Wq; Th = g_Wt_h;                               N = HID;    break;
        case 1: W = Wk; Th = g_Wt_h + (size_t)HID * HID;           N = KV_DIM; break;
        case 2: W = Wv; Th = g_Wt_h + (size_t)(HID + 512) * HID;   N = KV_DIM; break;
        default: W = Wo; Th = g_Wo_h;                              N = HID;    break;
    }
    int n0 = blockIdx.x * 32, k0 = blockIdx.y * 32;
    if (n0 >= N) return;
    __shared__ float t[32][33];
    int tx = threadIdx.x, ty = threadIdx.y;
#pragma unroll
    for (int i = 0; i < 32; i += 8)
        t[ty + i][tx] = W[(size_t)(k0 + ty + i) * N + n0 + tx];
    __syncthreads();
#pragma unroll
    for (int i = 0; i < 32; i += 8) {
        int n = n0 + ty + i, k = k0 + tx;
        Th[(size_t)n * HID + k] = __float2half_rn(t[tx][ty + i]);
    }
}

// ---------------- fp16x2 HMMA GEMM: BK=64, 2-stage, single barrier ----------
#define GSWZ(r, u) (((r) << 7) + ((((u) ^ (r)) & 7) << 4))
#define GTILE 16384
#define GSTG  (3 * GTILE)
#define GEMM_SMEM (2 * GSTG)       // 98304 -> 2 CTAs/SM

__device__ __forceinline__ void gemm_mainloop(
    const __half* __restrict__ Ah, const __half* __restrict__ Al,
    const __half* __restrict__ Bh,
    int Kd, int bm, int bnB, float acc[4][8][4], char* smem)
{
    const uint32_t sbase = smem_u32(smem);
    const int tid  = threadIdx.x;
    const int wid  = tid >> 5;
    const int lane = tid & 31;
    const int nch  = Kd >> 6;

    const int mw = (wid >> 1) * 64;
    const int nw = (wid & 1) * 64;

    const int rowA = mw + (lane & 15);
    const int uA   = (lane >> 4) & 1;
    const int rowB = nw + (lane & 7) + ((lane >> 4) << 3);
    const int uB   = (lane >> 3) & 1;

#pragma unroll
    for (int mt = 0; mt < 4; ++mt)
#pragma unroll
        for (int nb = 0; nb < 8; ++nb)
#pragma unroll
            for (int q = 0; q < 4; ++q) acc[mt][nb][q] = 0.f;

    auto load_stage = [&](int ci, int slot) {
        const int k0 = ci << 6;
        const uint32_t st = sbase + slot * GSTG;
#pragma unroll
        for (int it = 0; it < 24; ++it) {
            int u = tid + it * 128;
            int mat = u >> 10;
            int v = u & 1023;
            int row = v >> 3;
            int seg = v & 7;
            const __half* src;
            if (mat == 0)      src = Ah + (size_t)(bm + row) * Kd + k0 + seg * 8;
            else if (mat == 1) src = Al + (size_t)(bm + row) * Kd + k0 + seg * 8;
            else               src = Bh + (size_t)(bnB + row) * Kd + k0 + seg * 8;
            cp_async16(st + mat * GTILE + GSWZ(row, seg), src);
        }
        CP_COMMIT();
    };

    load_stage(0, 0);

    for (int i = 0; i < nch; ++i) {
        CP_WAIT(0);
        __syncthreads();
        if (i + 1 < nch) load_stage(i + 1, (i + 1) & 1);

        const uint32_t sb = sbase + (i & 1) * GSTG;
#pragma unroll
        for (int kk2 = 0; kk2 < 4; ++kk2) {
            uint32_t fAh[4][4], fAl[4][4];
#pragma unroll
            for (int mt = 0; mt < 4; ++mt) {
                uint32_t sw = GSWZ(rowA + mt * 16, kk2 * 2 + uA);
                ldm4(fAh[mt], sb + sw);
                ldm4(fAl[mt], sb + GTILE + sw);
            }
#pragma unroll
            for (int np = 0; np < 4; ++np) {
                uint32_t fB[4];
                uint32_t sw = GSWZ(np * 16 + rowB, kk2 * 2 + uB);
                ldm4(fB, sb + 2 * GTILE + sw);
#pragma unroll
                for (int half = 0; half < 2; ++half) {
                    int nb = np * 2 + half;
#pragma unroll
                    for (int mt = 0; mt < 4; ++mt)
                        mma16816h(acc[mt][nb], fAh[mt], &fB[half * 2]);
#pragma unroll
                    for (int mt = 0; mt < 4; ++mt)
                        mma16816h(acc[mt][nb], fAl[mt], &fB[half * 2]);
                }
            }
        }
    }
    __syncthreads();
}

// ---- QKV GEMM with fused RoPE (table) + bf16 hi/lo split epilogue ----------
__global__ __launch_bounds__(128) void qkv_gemm_kernel()
{
    extern __shared__ char smem[];
    const int bn = blockIdx.x * 128;
    const int bm = blockIdx.y * 128;

    float acc[4][8][4];
    gemm_mainloop(g_Xhi, g_Xlo, g_Wt_h, HID, bm, bn, acc, smem);

    const int tid  = threadIdx.x;
    const int wid  = tid >> 5;
    const int lane = tid & 31;
    const int mw = (wid >> 1) * 64;
    const int nw = (wid & 1) * 64;

    float* sm = (float*)smem;
#pragma unroll
    for (int mt = 0; mt < 4; ++mt)
#pragma unroll
        for (int nb = 0; nb < 8; ++nb) {
            int r0 = mw + mt * 16 + (lane >> 2);
            int c0 = nw + nb * 8 + (lane & 3) * 2;
            *(float2*)&sm[r0 * 132 + c0]       = make_float2(acc[mt][nb][0], acc[mt][nb][1]);
            *(float2*)&sm[(r0 + 8) * 132 + c0] = make_float2(acc[mt][nb][2], acc[mt][nb][3]);
        }
    __syncthreads();

    const bool isV = (bn >= HID + 512);
    __nv_bfloat16 *Dh, *Dl;
    int ldd, cbase;
    if (bn < HID)            { Dh = g_Qh; Dl = g_Ql; ldd = HID;    cbase = bn; }
    else if (bn < HID + 512) { Dh = g_Kh; Dl = g_Kl; ldd = KV_DIM; cbase = bn - HID; }
    else                     { Dh = g_Vh; Dl = g_Vl; ldd = KV_DIM; cbase = bn - HID - 512; }

#pragma unroll
    for (int k = 0; k < 16; ++k) {
        int u = tid + k * 128;
        int row = u >> 4;
        int i0 = (u & 15) * 4;
        float y0[4], y1[4];
        if (!isV) {
            float4 cv = *(const float4*)&g_rope_cos[(size_t)(bm + row) * 64 + i0];
            float4 sv = *(const float4*)&g_rope_sin[(size_t)(bm + row) * 64 + i0];
            float c[4] = {cv.x, cv.y, cv.z, cv.w};
            float s[4] = {sv.x, sv.y, sv.z, sv.w};
#pragma unroll
            for (int j = 0; j < 4; ++j) {
                float x0 = sm[row * 132 + i0 + j];
                float x1 = sm[row * 132 + i0 + j + 64];
                y0[j] = x0 * c[j] - x1 * s[j];
                y1[j] = x1 * c[j] + x0 * s[j];
            }
        } else {
#pragma unroll
            for (int j = 0; j < 4; ++j) {
                y0[j] = sm[row * 132 + i0 + j];
                y1[j] = sm[row * 132 + i0 + j + 64];
            }
        }
        size_t d0 = (size_t)(bm + row) * ldd + cbase + i0;
        size_t d1 = d0 + 64;
        __nv_bfloat16 h[8]; float r[8];
#pragma unroll
        for (int j = 0; j < 4; ++j) {
            h[j]     = __float2bfloat16(y0[j]);
            r[j]     = y0[j] - __bfloat162float(h[j]);
            h[j + 4] = __float2bfloat16(y1[j]);
            r[j + 4] = y1[j] - __bfloat162float(h[j + 4]);
        }
        *(__nv_bfloat162*)&Dh[d0]     = __halves2bfloat162(h[0], h[1]);
        *(__nv_bfloat162*)&Dh[d0 + 2] = __halves2bfloat162(h[2], h[3]);
        *(__nv_bfloat162*)&Dh[d1]     = __halves2bfloat162(h[4], h[5]);
        *(__nv_bfloat162*)&Dh[d1 + 2] = __halves2bfloat162(h[6], h[7]);
        *(__nv_bfloat162*)&Dl[d0]     = __floats2bfloat162_rn(r[0], r[1]);
        *(__nv_bfloat162*)&Dl[d0 + 2] = __floats2bfloat162_rn(r[2], r[3]);
        *(__nv_bfloat162*)&Dl[d1]     = __floats2bfloat162_rn(r[4], r[5]);
        *(__nv_bfloat162*)&Dl[d1 + 2] = __floats2bfloat162_rn(r[6], r[7]);
    }
}

// ---- output projection GEMM (direct fp32 store epilogue) --------------------
__global__ __launch_bounds__(128) void out_gemm_kernel(float* __restrict__ out)
{
    extern __shared__ char smem[];
    const int bn = blockIdx.x * 128;
    const int bm = blockIdx.y * 128;

    float acc[4][8][4];
    gemm_mainloop(g_Ahi, g_Alo, g_Wo_h, HID, bm, bn, acc, smem);

    const int tid  = threadIdx.x;
    const int wid  = tid >> 5;
    const int lane = tid & 31;
    const int mw = (wid >> 1) * 64;
    const int nw = (wid & 1) * 64;

#pragma unroll
    for (int mt = 0; mt < 4; ++mt)
#pragma unroll
        for (int nb = 0; nb < 8; ++nb) {
            int r0 = bm + mw + mt * 16 + (lane >> 2);
            int c0 = bn + nw + nb * 8 + (lane & 3) * 2;
            float2 v0 = {acc[mt][nb][0], acc[mt][nb][1]};
            float2 v1 = {acc[mt][nb][2], acc[mt][nb][3]};
            *(float2*)(out + (size_t)r0 * HID + c0)       = v0;
            *(float2*)(out + (size_t)(r0 + 8) * HID + c0) = v1;
        }
}

// ---------------- flash v2: BM=128, 8 warps, cp.async 2-stage KV -------------
// Q: Qh|Ql 128x256B swizzled (32 KB each). KV stage: Kh|Kl|Vh|Vl 64x256B (16 KB each).
#define FSWZ(r, cb) ((((r) << 8) + (cb)) ^ (((r) & 7) << 4))
#define F_QH 0
#define F_QL 32768
#define F_KV 65536                 // + slot*65536; within: KH 0 KL 16384 VH 32768 VL 49152
#define FLASH_SMEM 196608          // 192 KB -> 1 CTA/SM, 8 warps

__global__ __launch_bounds__(256) void flash_kernel()
{
    const int qt  = (int)gridDim.x - 1 - (int)blockIdx.x;   // heavy tiles first
    const int h   = blockIdx.y;
    const int kvh = h / (NH / NKV);

    extern __shared__ char fsm[];
    const uint32_t sbv = smem_u32(fsm);

    const int tid  = threadIdx.x;
    const int w    = tid >> 5;      // 0..7, warp rows = w*16..w*16+15 of 128
    const int lane = tid & 31;

    const int rowA   = w * 16 + (lane & 15);
    const int colA   = (lane >> 4) << 3;
    const int rowBo  = (lane & 7) + ((lane >> 4) << 3);
    const int colB   = ((lane >> 3) & 1) << 3;
    const int rowVt  = (lane & 7) + (((lane >> 3) & 1) << 3);
    const int colVt  = (lane >> 4) << 3;

    // load Q tile (128 rows, hi/lo) — one-time synchronous
    for (int f = tid; f < 2048; f += 256) {
        int r = f >> 4, cb = (f & 15) * 16;
        size_t g = (size_t)(qt * 128 + r) * HID + h * 128 + (f & 15) * 8;
        *(uint4*)(fsm + F_QH + FSWZ(r, cb)) = *(const uint4*)&g_Qh[g];
        *(uint4*)(fsm + F_QL + FSWZ(r, cb)) = *(const uint4*)&g_Ql[g];
    }

    const int nkt = 2 * qt + 2;

    // cp.async KV stage loader: 4096 x 16B, 16 per thread
    auto load_kv = [&](int kt, int slot) {
        const uint32_t st = sbv + F_KV + slot * 65536;
#pragma unroll
        for (int it = 0; it < 16; ++it) {
            int u = tid + it * 256;
            int arr = u >> 10;           // 0 Kh, 1 Kl, 2 Vh, 3 Vl
            int v = u & 1023;
            int r = v >> 4, seg = v & 15;
            size_t g = (size_t)(kt * 64 + r) * KV_DIM + kvh * 128 + seg * 8;
            const __nv_bfloat16* src;
            if (arr == 0)      src = &g_Kh[g];
            else if (arr == 1) src = &g_Kl[g];
            else if (arr == 2) src = &g_Vh[g];
            else               src = &g_Vl[g];
            cp_async16(st + arr * 16384 + FSWZ(r, seg * 16), src);
        }
        CP_COMMIT();
    };

    load_kv(0, 0);

    float o[16][4];
#pragma unroll
    for (int nb = 0; nb < 16; ++nb)
#pragma unroll
        for (int q = 0; q < 4; ++q) o[nb][q] = 0.f;
    float m0 = -1e30f, m1 = -1e30f, l0 = 0.f, l1 = 0.f;

    const float SL = 0.08838834764831845f * 1.4426950408889634f;

    for (int kt = 0; kt < nkt; ++kt) {
        CP_WAIT(0);                 // stage kt resident
        __syncthreads();            // all warps done with stage kt-1 (slot reuse safe)
        if (kt + 1 < nkt) load_kv(kt + 1, (kt + 1) & 1);

        const uint32_t kb_ = sbv + F_KV + (kt & 1) * 65536;
        const uint32_t sKH = kb_, sKL = kb_ + 16384, sVH = kb_ + 32768, sVL = kb_ + 49152;

        // ---- S = Q K^T (bf16x3) ----
        float s[8][4];
#pragma unroll
        for (int nb = 0; nb < 8; ++nb)
#pragma unroll
            for (int q = 0; q < 4; ++q) s[nb][q] = 0.f;

#pragma unroll
        for (int ks = 0; ks < 8; ++ks) {
            uint32_t qh[4], ql[4];
            uint32_t swa = FSWZ(rowA, ks * 32 + colA * 2);
            ldm4(qh, sbv + F_QH + swa);
            ldm4(ql, sbv + F_QL + swa);
#pragma unroll
            for (int np = 0; np < 4; ++np) {
                uint32_t kh[4], kl[4];
                uint32_t swb = FSWZ(np * 16 + rowBo, ks * 32 + colB * 2);
                ldm4(kh, sKH + swb);
                ldm4(kl, sKL + swb);
#pragma unroll
                for (int half = 0; half < 2; ++half) {
                    int nb = np * 2 + half;
                    mma16816(s[nb], qh, &kh[half * 2]);
                    mma16816(s[nb], qh, &kl[half * 2]);
                    mma16816(s[nb], ql, &kh[half * 2]);
                }
            }
        }

        // ---- online softmax (relative row/col; mask only on last two tiles) ----
        const bool diag = (kt >= 2 * qt);
        const int lrow0 = w * 16 + (lane >> 2);       // 0..127
        const int lrow1 = lrow0 + 8;
        const int lcb   = (kt - 2 * qt) * 64;         // relative col base
        float mx0 = -1e30f, mx1 = -1e30f;
#pragma unroll
        for (int nb = 0; nb < 8; ++nb) {
            int c0 = lcb + nb * 8 + (lane & 3) * 2;
#pragma unroll
            for (int q = 0; q < 4; ++q) {
                float v = s[nb][q] * SL;
                if (diag) {
                    int col = c0 + (q & 1);
                    int row = (q < 2) ? lrow0 : lrow1;
                    if (col > row) v = -1e30f;
                }
                s[nb][q] = v;
            }
            mx0 = fmaxf(mx0, fmaxf(s[nb][0], s[nb][1]));
            mx1 = fmaxf(mx1, fmaxf(s[nb][2], s[nb][3]));
        }
        mx0 = fmaxf(mx0, __shfl_xor_sync(0xffffffffu, mx0, 1));
        mx0 = fmaxf(mx0, __shfl_xor_sync(0xffffffffu, mx0, 2));
        mx1 = fmaxf(mx1, __shfl_xor_sync(0xffffffffu, mx1, 1));
        mx1 = fmaxf(mx1, __shfl_xor_sync(0xffffffffu, mx1, 2));

        float mn0 = fmaxf(m0, mx0), mn1 = fmaxf(m1, mx1);
        float a0 = exp2f(m0 - mn0), a1 = exp2f(m1 - mn1);
        float ls0 = 0.f, ls1 = 0.f;
#pragma unroll
        for (int nb = 0; nb < 8; ++nb) {
            float p0 = exp2f(s[nb][0] - mn0);
            float p1 = exp2f(s[nb][1] - mn0);
            float p2 = exp2f(s[nb][2] - mn1);
            float p3 = exp2f(s[nb][3] - mn1);
            s[nb][0] = p0; s[nb][1] = p1; s[nb][2] = p2; s[nb][3] = p3;
            ls0 += p0 + p1;
            ls1 += p2 + p3;
        }
        ls0 += __shfl_xor_sync(0xffffffffu, ls0, 1);
        ls0 += __shfl_xor_sync(0xffffffffu, ls0, 2);
        ls1 += __shfl_xor_sync(0xffffffffu, ls1, 1);
        ls1 += __shfl_xor_sync(0xffffffffu, ls1, 2);
        l0 = l0 * a0 + ls0;
        l1 = l1 * a1 + ls1;
        m0 = mn0; m1 = mn1;

#pragma unroll
        for (int nb = 0; nb < 16; ++nb) {
            o[nb][0] *= a0; o[nb][1] *= a0;
            o[nb][2] *= a1; o[nb][3] *= a1;
        }

        // ---- pack P into bf16 hi/lo A-fragments ----
        uint32_t pah[4][4], pal[4][4];
#pragma unroll
        for (int kb = 0; kb < 4; ++kb) {
#pragma unroll
            for (int part = 0; part < 4; ++part) {
                int nb = 2 * kb + (part >> 1);
                float c0 = s[nb][(part & 1) * 2];
                float c1 = s[nb][(part & 1) * 2 + 1];
                __nv_bfloat162 hi2 = __floats2bfloat162_rn(c0, c1);
                pah[kb][part] = *(uint32_t*)&hi2;
                float r0 = c0 - __bfloat162float(hi2.x);
                float r1 = c1 - __bfloat162float(hi2.y);
                pal[kb][part] = packbf2(r0, r1);
            }
        }

        // ---- O += P V (bf16x3) ----
#pragma unroll
        for (int kb = 0; kb < 4; ++kb) {
#pragma unroll
            for (int nv = 0; nv < 8; ++nv) {
                uint32_t vh[4], vl[4];
                uint32_t swv = FSWZ(kb * 16 + rowVt, nv * 32 + colVt * 2);
                ldm4t(vh, sVH + swv);
                ldm4t(vl, sVL + swv);
#pragma unroll
                for (int half = 0; half < 2; ++half) {
                    int nbv = nv * 2 + half;
                    mma16816(o[nbv], pah[kb], &vh[half * 2]);
                    mma16816(o[nbv], pal[kb], &vh[half * 2]);
                    mma16816(o[nbv], pah[kb], &vl[half * 2]);
                }
            }
        }
    }

    // normalize + write fp16 hi/lo for the fp16x2 out-projection
    const float inv0 = 1.0f / l0, inv1 = 1.0f / l1;
    const int r0 = qt * 128 + w * 16 + (lane >> 2);
    const int r1 = r0 + 8;
#pragma unroll
    for (int nb = 0; nb < 16; ++nb) {
        int c = h * 128 + nb * 8 + (lane & 3) * 2;
        float y0 = o[nb][0] * inv0, y1 = o[nb][1] * inv0;
        float y2 = o[nb][2] * inv1, y3 = o[nb][3] * inv1;
        __half2 h01 = __floats2half2_rn(y0, y1);
        __half2 h23 = __floats2half2_rn(y2, y3);
        *(__half2*)&g_Ahi[(size_t)r0 * HID + c] = h01;
        *(__half2*)&g_Ahi[(size_t)r1 * HID + c] = h23;
        __half2 l01 = __floats2half2_rn(y0 - __half2float(__low2half(h01)),
                                        y1 - __half2float(__high2half(h01)));
        __half2 l23 = __floats2half2_rn(y2 - __half2float(__low2half(h23)),
                                        y3 - __half2float(__high2half(h23)));
        *(__half2*)&g_Alo[(size_t)r0 * HID + c] = l01;
        *(__half2*)&g_Alo[(size_t)r1 * HID + c] = l23;
    }
}

// ---------------------------------------------------------------------------
extern "C" void kernel_launch(void* const* d_in, const int* in_sizes, int n_in,
                              void* d_out, int out_size)
{
    const float* X   = (const float*)d_in[0];
    const int*   pid = (const int*)  d_in[1];
    const float* Wq  = (const float*)d_in[2];
    const float* Wk  = (const float*)d_in[3];
    const float* Wv  = (const float*)d_in[4];
    const float* Wo  = (const float*)d_in[5];
    float* out = (float*)d_out;

    static int attr_set = 0;
    if (!attr_set) {
        cudaFuncSetAttribute(qkv_gemm_kernel, cudaFuncAttributeMaxDynamicSharedMemorySize, GEMM_SMEM);
        cudaFuncSetAttribute(out_gemm_kernel, cudaFuncAttributeMaxDynamicSharedMemorySize, GEMM_SMEM);
        cudaFuncSetAttribute(flash_kernel, cudaFuncAttributeMaxDynamicSharedMemorySize, FLASH_SMEM);
        attr_set = 1;
    }

    split_x_kernel<<<(S_LEN * HID + 255) / 256, 256>>>(X);
    transpose_all<<<dim3(HID / 32, HID / 32, 4), dim3(32, 8)>>>(Wq, Wk, Wv, Wo);
    rope_table_kernel<<<(S_LEN * 64 + 255) / 256, 256>>>(pid);

    qkv_gemm_kernel<<<dim3(QKV_N / 128, S_LEN / 128), 128, GEMM_SMEM>>>();

    flash_kernel<<<dim3(16, 28), 256, FLASH_SMEM>>>();

    out_gemm_kernel<<<dim3(HID / 128, S_LEN / 128), 128, GEMM_SMEM>>>(out);
}